// round 5
// baseline (speedup 1.0000x reference)
#include <cuda_runtime.h>
#include <cuda_fp16.h>
#include <math_constants.h>
#include <cstdint>

// Problem constants
#define BB 8
#define TT 2048
#define EE 1024
#define NQKV ((size_t)BB * TT * EE)   // 16,777,216
#define NS   ((size_t)BB * TT * TT)   // 33,554,432

// ---------------------------------------------------------------------------
// Scratch (device globals; allocation forbidden in kernel_launch)
// ---------------------------------------------------------------------------
__device__ __half g_qh[NQKV], g_ql[NQKV];
__device__ __half g_kh[NQKV], g_kl[NQKV];
__device__ __half g_vh[NQKV], g_vl[NQKV];
__device__ __half g_Wqh[EE * EE], g_Wql[EE * EE];
__device__ __half g_Wkh[EE * EE], g_Wkl[EE * EE];
__device__ __half g_Wvh[EE * EE], g_Wvl[EE * EE];
__device__ __half g_Qh[NQKV], g_Ql[NQKV];
__device__ __half g_Kh[NQKV], g_Kl[NQKV];
__device__ float  g_V[NQKV];
__device__ __half g_VTh[NQKV], g_VTl[NQKV];
__device__ float  g_S[NS];
__device__ __half g_Ph[NS], g_Pl[NS];

// ---------------------------------------------------------------------------
// Helpers
// ---------------------------------------------------------------------------
__device__ __forceinline__ uint32_t smem_u32(const void* p) {
    uint32_t a;
    asm("{ .reg .u64 t; cvta.to.shared.u64 t, %1; cvt.u32.u64 %0, t; }"
        : "=r"(a) : "l"(p));
    return a;
}

__device__ __forceinline__ void cp16(uint32_t dst_smem, const void* src_gmem) {
    asm volatile("cp.async.cg.shared.global [%0], [%1], 16;"
                 :: "r"(dst_smem), "l"(__cvta_generic_to_global(src_gmem)));
}
#define CP_COMMIT() asm volatile("cp.async.commit_group;" ::: "memory")
#define CP_WAIT1()  asm volatile("cp.async.wait_group 1;"  ::: "memory")

// ldmatrix x4 (non-transposed, b16)
__device__ __forceinline__ void ldsm4(uint32_t* r, uint32_t addr) {
    asm volatile("ldmatrix.sync.aligned.m8n8.x4.shared.b16 {%0,%1,%2,%3}, [%4];"
                 : "=r"(r[0]), "=r"(r[1]), "=r"(r[2]), "=r"(r[3]) : "r"(addr));
}

// m16n8k16 fp16 -> fp32 accumulate
__device__ __forceinline__ void mma16816(float* c,
                                         uint32_t a0, uint32_t a1, uint32_t a2, uint32_t a3,
                                         uint32_t b0, uint32_t b1) {
    asm volatile(
        "mma.sync.aligned.m16n8k16.row.col.f32.f16.f16.f32 "
        "{%0,%1,%2,%3}, {%4,%5,%6,%7}, {%8,%9}, {%0,%1,%2,%3};"
        : "+f"(c[0]), "+f"(c[1]), "+f"(c[2]), "+f"(c[3])
        : "r"(a0), "r"(a1), "r"(a2), "r"(a3), "r"(b0), "r"(b1));
}

// m16n8k16 fp16 -> fp16 accumulate (for small correction terms)
__device__ __forceinline__ void mma16816h(uint32_t* c,
                                          uint32_t a0, uint32_t a1, uint32_t a2, uint32_t a3,
                                          uint32_t b0, uint32_t b1) {
    asm volatile(
        "mma.sync.aligned.m16n8k16.row.col.f16.f16.f16.f16 "
        "{%0,%1}, {%2,%3,%4,%5}, {%6,%7}, {%0,%1};"
        : "+r"(c[0]), "+r"(c[1])
        : "r"(a0), "r"(a1), "r"(a2), "r"(a3), "r"(b0), "r"(b1));
}

__device__ __forceinline__ void split2(float x, __half& h, __half& l) {
    h = __float2half_rn(x);
    l = __float2half_rn(x - __half2float(h));
}

// ---------------------------------------------------------------------------
// Fused elementwise split: fp32 -> (hi, lo) fp16, 3 arrays per launch (z).
// Grid-stride, 8 floats per thread per step. n % 8 == 0.
// ---------------------------------------------------------------------------
struct SplitArgs {
    const float* src[3];
    __half* hi[3];
    __half* lo[3];
    size_t n;
};

__global__ __launch_bounds__(256)
void split3_kernel(SplitArgs a)
{
    const int z = blockIdx.z;
    const float* __restrict__ x = a.src[z];
    __half* __restrict__ hi = a.hi[z];
    __half* __restrict__ lo = a.lo[z];
    const size_t n = a.n;
    const size_t stride = (size_t)gridDim.x * blockDim.x * 8;

    for (size_t i = ((size_t)blockIdx.x * blockDim.x + threadIdx.x) * 8;
         i < n; i += stride) {
#pragma unroll
        for (int w = 0; w < 2; w++) {
            float4 v = *(const float4*)(x + i + w * 4);
            __half h0, h1, h2, h3, l0, l1, l2, l3;
            split2(v.x, h0, l0); split2(v.y, h1, l1);
            split2(v.z, h2, l2); split2(v.w, h3, l3);
            __half2* ph = (__half2*)(hi + i + w * 4);
            __half2* pl = (__half2*)(lo + i + w * 4);
            ph[0] = __halves2half2(h0, h1);
            ph[1] = __halves2half2(h2, h3);
            pl[0] = __halves2half2(l0, l1);
            pl[1] = __halves2half2(l2, l3);
        }
    }
}

// ---------------------------------------------------------------------------
// Split-FP16 NT GEMM on tensor cores:
//   C[M,N] = alpha * (Ah+Al)[M,K] * (Bh+Bl)[N,K]^T
// Main term Ah*Bh in fp32-accum HMMA; corrections Ah*Bl + Al*Bh in
// fp16-accum HMMA (values ~2^-11 of main term), folded in at epilogue.
// CTA: 128x128x32, 256 threads = 8 warps (2 x 4), warp tile 64x32.
// SMEM: 3 stages x 4 tiles (Ah, Al, Bh, Bl), each 128 rows x 80B.
// OUT_MODE 0: write fp32 C.  OUT_MODE 1: write split fp16 (Ch, Cl).
// Requires M%128==0, N%128==0, K%32==0.
// ---------------------------------------------------------------------------
#define SROW 80
#define TILE_B (128 * SROW)            // 10240
#define STAGE_B (4 * TILE_B)           // 40960
#define GEMM_SMEM (3 * STAGE_B)        // 122880

template <int OUT_MODE>
__global__ __launch_bounds__(256, 1)
void gemm_f16pair_nt(const __half* __restrict__ Ah, const __half* __restrict__ Al,
                     const __half* __restrict__ Bh, const __half* __restrict__ Bl,
                     float* __restrict__ C, __half* __restrict__ Ch,
                     __half* __restrict__ Cl,
                     int M, int N, int K, float alpha,
                     size_t sA, size_t sB, size_t sC)
{
    extern __shared__ __align__(128) char smem[];
    const uint32_t sb = smem_u32(smem);

    const int tid  = threadIdx.x;
    const int wid  = tid >> 5;
    const int lane = tid & 31;
    const int wm   = wid >> 2;          // 0..1
    const int wn   = wid & 3;           // 0..3
    const int g    = lane >> 2;         // 0..7
    const int i4   = lane & 3;          // 0..3

    const size_t z = blockIdx.z;
    const __half* pAh = Ah + z * sA;
    const __half* pAl = Al + z * sA;
    const __half* pBh = Bh + z * sB;
    const __half* pBl = Bl + z * sB;

    const int aRow0 = blockIdx.y * 128;
    const int bRow0 = blockIdx.x * 128;

    // cp.async copy indices
    const int cr0 = tid >> 2;            // rows 0..63
    const int cq  = (tid & 3);           // 16B quarter 0..3

    // ldmatrix per-lane address offsets
    const int lmA = lane & 15;
    const int lqA = (lane >> 4) & 1;
    uint32_t aoff[4];
#pragma unroll
    for (int fm = 0; fm < 4; fm++)
        aoff[fm] = (uint32_t)((wm * 64 + fm * 16 + lmA) * SROW + lqA * 16);
    const int bn = (lane & 7) + ((lane >> 4) << 3);
    const int bq = (lane >> 3) & 1;
    uint32_t boff[2];
#pragma unroll
    for (int fp = 0; fp < 2; fp++)
        boff[fp] = (uint32_t)((wn * 32 + fp * 16 + bn) * SROW + bq * 16);

    float acc[4][4][4];
    uint32_t crr[4][4][2];
#pragma unroll
    for (int a = 0; a < 4; a++)
#pragma unroll
        for (int b = 0; b < 4; b++) {
#pragma unroll
            for (int c = 0; c < 4; c++) acc[a][b][c] = 0.0f;
            crr[a][b][0] = 0u; crr[a][b][1] = 0u;
        }

    const int nch = K >> 5;

    auto issue = [&](int kc) {
        const uint32_t tb = sb + (uint32_t)(kc % 3) * STAGE_B;
        const int kofs = kc << 5;
#pragma unroll
        for (int t = 0; t < 2; t++) {
            const int r = cr0 + t * 64;
            const uint32_t so = (uint32_t)(r * SROW + cq * 16);
            const size_t goA = (size_t)(aRow0 + r) * K + kofs + cq * 8;
            const size_t goB = (size_t)(bRow0 + r) * K + kofs + cq * 8;
            cp16(tb + 0 * TILE_B + so, pAh + goA);
            cp16(tb + 1 * TILE_B + so, pAl + goA);
            cp16(tb + 2 * TILE_B + so, pBh + goB);
            cp16(tb + 3 * TILE_B + so, pBl + goB);
        }
        CP_COMMIT();
    };

    issue(0);
    issue(1);

    for (int kc = 0; kc < nch; kc++) {
        CP_WAIT1();
        __syncthreads();
        if (kc + 2 < nch) issue(kc + 2);

        const uint32_t tb = sb + (uint32_t)(kc % 3) * STAGE_B;
#pragma unroll
        for (int h = 0; h < 2; h++) {
            const uint32_t ho = (uint32_t)(h * 32);
            uint32_t ah[4][4], al[4][4];
#pragma unroll
            for (int fm = 0; fm < 4; fm++) {
                ldsm4(ah[fm], tb + 0 * TILE_B + aoff[fm] + ho);
                ldsm4(al[fm], tb + 1 * TILE_B + aoff[fm] + ho);
            }
            uint32_t bh[2][4], bl[2][4];
#pragma unroll
            for (int fp = 0; fp < 2; fp++) {
                ldsm4(bh[fp], tb + 2 * TILE_B + boff[fp] + ho);
                ldsm4(bl[fp], tb + 3 * TILE_B + boff[fp] + ho);
            }
#pragma unroll
            for (int fn = 0; fn < 4; fn++) {
                const uint32_t b0h = bh[fn >> 1][(fn & 1) * 2];
                const uint32_t b1h = bh[fn >> 1][(fn & 1) * 2 + 1];
                const uint32_t b0l = bl[fn >> 1][(fn & 1) * 2];
                const uint32_t b1l = bl[fn >> 1][(fn & 1) * 2 + 1];
#pragma unroll
                for (int fm = 0; fm < 4; fm++) {
                    // main: fp32 accumulate
                    mma16816(acc[fm][fn], ah[fm][0], ah[fm][1], ah[fm][2], ah[fm][3], b0h, b1h);
                    // corrections: fp16 accumulate (tiny values)
                    mma16816h(crr[fm][fn], ah[fm][0], ah[fm][1], ah[fm][2], ah[fm][3], b0l, b1l);
                    mma16816h(crr[fm][fn], al[fm][0], al[fm][1], al[fm][2], al[fm][3], b0h, b1h);
                }
            }
        }
        __syncthreads();
    }

    // Epilogue: fold fp16 corrections into fp32 accumulators, scale, store
    const int rowB = aRow0 + wm * 64 + g;
    const int colB = bRow0 + wn * 32 + i4 * 2;
#pragma unroll
    for (int fm = 0; fm < 4; fm++) {
#pragma unroll
        for (int fn = 0; fn < 4; fn++) {
            const int row = rowB + fm * 16;
            const int col = colB + fn * 8;
            float2 k0 = __half22float2(*(__half2*)&crr[fm][fn][0]);
            float2 k1 = __half22float2(*(__half2*)&crr[fm][fn][1]);
            float c0 = alpha * (acc[fm][fn][0] + k0.x);
            float c1 = alpha * (acc[fm][fn][1] + k0.y);
            float c2 = alpha * (acc[fm][fn][2] + k1.x);
            float c3 = alpha * (acc[fm][fn][3] + k1.y);
            if (OUT_MODE == 0) {
                float* pc = C + z * sC;
                *(float2*)(pc + (size_t)row * N + col)       = make_float2(c0, c1);
                *(float2*)(pc + (size_t)(row + 8) * N + col) = make_float2(c2, c3);
            } else {
                __half* ph = Ch + z * sC;
                __half* pl = Cl + z * sC;
                __half h0, h1, h2, h3, l0, l1, l2, l3;
                split2(c0, h0, l0); split2(c1, h1, l1);
                split2(c2, h2, l2); split2(c3, h3, l3);
                *(__half2*)(ph + (size_t)row * N + col)       = __halves2half2(h0, h1);
                *(__half2*)(pl + (size_t)row * N + col)       = __halves2half2(l0, l1);
                *(__half2*)(ph + (size_t)(row + 8) * N + col) = __halves2half2(h2, h3);
                *(__half2*)(pl + (size_t)(row + 8) * N + col) = __halves2half2(l2, l3);
            }
        }
    }
}

// ---------------------------------------------------------------------------
// Transpose + split: V[b][s][o] fp32 -> VThi/VTlo[b][o][s] fp16
// ---------------------------------------------------------------------------
__global__ __launch_bounds__(256)
void transpose_split_kernel(const float* __restrict__ V,
                            __half* __restrict__ Th, __half* __restrict__ Tl)
{
    __shared__ float t[32][33];
    const int b  = blockIdx.z;
    const int s0 = blockIdx.x << 5;
    const int o0 = blockIdx.y << 5;
    const float* Vb = V + (size_t)b * TT * EE;
    __half* Thb = Th + (size_t)b * EE * TT;
    __half* Tlb = Tl + (size_t)b * EE * TT;
    const int tx = threadIdx.x & 31;
    const int ty = threadIdx.x >> 5;
#pragma unroll
    for (int i = 0; i < 4; i++)
        t[ty + 8 * i][tx] = Vb[(size_t)(s0 + ty + 8 * i) * EE + o0 + tx];
    __syncthreads();
#pragma unroll
    for (int i = 0; i < 4; i++) {
        float x = t[tx][ty + 8 * i];
        __half h, l;
        split2(x, h, l);
        const size_t off = (size_t)(o0 + ty + 8 * i) * TT + s0 + tx;
        Thb[off] = h;
        Tlb[off] = l;
    }
}

// ---------------------------------------------------------------------------
// Masked row softmax: S[B*T, T] fp32 -> split fp16 (Ph, Pl). mask 0 -> -inf.
// ---------------------------------------------------------------------------
__global__ __launch_bounds__(256)
void softmax_split_kernel(const float* __restrict__ S, const int* __restrict__ mask,
                          __half* __restrict__ Ph, __half* __restrict__ Pl)
{
    const int row = blockIdx.x;
    const int t   = row & (TT - 1);
    const float* Srow = S + (size_t)row * TT;
    const int* mrow = mask + (size_t)t * TT;
    const int tid = threadIdx.x;

    float v[8];
    float m = -CUDART_INF_F;
#pragma unroll
    for (int i = 0; i < 8; i++) {
        int s = tid + i * 256;
        float x = (mrow[s] != 0) ? Srow[s] : -CUDART_INF_F;
        v[i] = x;
        m = fmaxf(m, x);
    }

    __shared__ float red[256];
    red[tid] = m;
    __syncthreads();
    for (int off = 128; off > 0; off >>= 1) {
        if (tid < off) red[tid] = fmaxf(red[tid], red[tid + off]);
        __syncthreads();
    }
    m = red[0];
    __syncthreads();

    float sum = 0.0f;
#pragma unroll
    for (int i = 0; i < 8; i++) {
        float e = __expf(v[i] - m);
        v[i] = e;
        sum += e;
    }
    red[tid] = sum;
    __syncthreads();
    for (int off = 128; off > 0; off >>= 1) {
        if (tid < off) red[tid] += red[tid + off];
        __syncthreads();
    }
    const float inv = 1.0f / red[0];

    __half* Phr = Ph + (size_t)row * TT;
    __half* Plr = Pl + (size_t)row * TT;
#pragma unroll
    for (int i = 0; i < 8; i++) {
        float p = v[i] * inv;
        __half h, l;
        split2(p, h, l);
        Phr[tid + i * 256] = h;
        Plr[tid + i * 256] = l;
    }
}

// ---------------------------------------------------------------------------
// kernel_launch
// Launch order (ncu -s 5 -c 1 profiles launch #6 = scores GEMM):
//   1 split3(q,k,v)  2 split3(W)  3 projQ  4 projK  5 projV
//   6 scores GEMM    7 transpose  8 softmax  9 PV GEMM
// ---------------------------------------------------------------------------
extern "C" void kernel_launch(void* const* d_in, const int* in_sizes, int n_in,
                              void* d_out, int out_size)
{
    const float* q    = (const float*)d_in[0];
    const float* k    = (const float*)d_in[1];
    const float* v    = (const float*)d_in[2];
    const int*   mask = (const int*)  d_in[3];
    const float* Wq   = (const float*)d_in[4];
    const float* Wk   = (const float*)d_in[5];
    const float* Wv   = (const float*)d_in[6];
    float* out = (float*)d_out;

    __half *qh, *ql, *kh, *kl, *vh, *vl;
    __half *wqh, *wql, *wkh, *wkl, *wvh, *wvl;
    __half *Qh, *Ql, *Kh, *Kl, *VTh, *VTl, *Ph, *Pl;
    float *V, *S;
    cudaGetSymbolAddress((void**)&qh,  g_qh);  cudaGetSymbolAddress((void**)&ql,  g_ql);
    cudaGetSymbolAddress((void**)&kh,  g_kh);  cudaGetSymbolAddress((void**)&kl,  g_kl);
    cudaGetSymbolAddress((void**)&vh,  g_vh);  cudaGetSymbolAddress((void**)&vl,  g_vl);
    cudaGetSymbolAddress((void**)&wqh, g_Wqh); cudaGetSymbolAddress((void**)&wql, g_Wql);
    cudaGetSymbolAddress((void**)&wkh, g_Wkh); cudaGetSymbolAddress((void**)&wkl, g_Wkl);
    cudaGetSymbolAddress((void**)&wvh, g_Wvh); cudaGetSymbolAddress((void**)&wvl, g_Wvl);
    cudaGetSymbolAddress((void**)&Qh,  g_Qh);  cudaGetSymbolAddress((void**)&Ql,  g_Ql);
    cudaGetSymbolAddress((void**)&Kh,  g_Kh);  cudaGetSymbolAddress((void**)&Kl,  g_Kl);
    cudaGetSymbolAddress((void**)&VTh, g_VTh); cudaGetSymbolAddress((void**)&VTl, g_VTl);
    cudaGetSymbolAddress((void**)&Ph,  g_Ph);  cudaGetSymbolAddress((void**)&Pl,  g_Pl);
    cudaGetSymbolAddress((void**)&V,   g_V);
    cudaGetSymbolAddress((void**)&S,   g_S);

    cudaFuncSetAttribute(gemm_f16pair_nt<0>,
                         cudaFuncAttributeMaxDynamicSharedMemorySize, GEMM_SMEM);
    cudaFuncSetAttribute(gemm_f16pair_nt<1>,
                         cudaFuncAttributeMaxDynamicSharedMemorySize, GEMM_SMEM);

    const int M = BB * TT;                   // 16384
    const size_t strQKV = (size_t)TT * EE;
    const size_t strS   = (size_t)TT * TT;
    const size_t strVT  = (size_t)EE * TT;

    // 1) Split q,k,v inputs (fused, grid.z selects array)
    {
        SplitArgs a;
        a.src[0] = q;  a.src[1] = k;  a.src[2] = v;
        a.hi[0] = qh;  a.hi[1] = kh;  a.hi[2] = vh;
        a.lo[0] = ql;  a.lo[1] = kl;  a.lo[2] = vl;
        a.n = NQKV;
        dim3 gs((unsigned)(NQKV / (256 * 8)), 1, 3);
        split3_kernel<<<gs, 256>>>(a);
    }
    // 2) Split weights (fused)
    {
        SplitArgs a;
        a.src[0] = Wq;  a.src[1] = Wk;  a.src[2] = Wv;
        a.hi[0] = wqh;  a.hi[1] = wkh;  a.hi[2] = wvh;
        a.lo[0] = wql;  a.lo[1] = wkl;  a.lo[2] = wvl;
        a.n = (size_t)EE * EE;
        dim3 gs((unsigned)((size_t)EE * EE / (256 * 8)), 1, 3);
        split3_kernel<<<gs, 256>>>(a);
    }

    // 3-5) Projections (M=16384, N=1024, K=1024)
    dim3 gProj(EE / 128, M / 128, 1);
    gemm_f16pair_nt<1><<<gProj, 256, GEMM_SMEM>>>(qh, ql, wqh, wql,
        nullptr, Qh, Ql, M, EE, EE, 1.0f, 0, 0, 0);
    gemm_f16pair_nt<1><<<gProj, 256, GEMM_SMEM>>>(kh, kl, wkh, wkl,
        nullptr, Kh, Kl, M, EE, EE, 1.0f, 0, 0, 0);
    gemm_f16pair_nt<0><<<gProj, 256, GEMM_SMEM>>>(vh, vl, wvh, wvl,
        V, nullptr, nullptr, M, EE, EE, 1.0f, 0, 0, 0);

    // 6) Scores: S_b = (Q_b K_b^T) / 32   (M=N=2048, K=1024, batched)
    dim3 gScore(TT / 128, TT / 128, BB);
    gemm_f16pair_nt<0><<<gScore, 256, GEMM_SMEM>>>(Qh, Ql, Kh, Kl,
        S, nullptr, nullptr, TT, TT, EE, 1.0f / 32.0f, strQKV, strQKV, strS);

    // 7) Transpose + split V -> VT (only needed before PV)
    dim3 gT(TT / 32, EE / 32, BB);
    transpose_split_kernel<<<gT, 256>>>(V, VTh, VTl);

    // 8) Masked softmax -> split fp16 P
    softmax_split_kernel<<<BB * TT, 256>>>(S, mask, Ph, Pl);

    // 9) Output: O_b = P_b VT_b^T  (M=2048, N=1024, K=2048, batched)
    dim3 gOut(EE / 128, TT / 128, BB);
    gemm_f16pair_nt<0><<<gOut, 256, GEMM_SMEM>>>(Ph, Pl, VTh, VTl,
        out, nullptr, nullptr, TT, EE, TT, 1.0f, strS, strVT, strQKV);
}

// round 6
// speedup vs baseline: 1.0073x; 1.0073x over previous
#include <cuda_runtime.h>
#include <cuda_fp16.h>
#include <math_constants.h>
#include <cstdint>

// Problem constants
#define BB 8
#define TT 2048
#define EE 1024
#define NQKV ((size_t)BB * TT * EE)   // 16,777,216
#define NS   ((size_t)BB * TT * TT)   // 33,554,432

// ---------------------------------------------------------------------------
// Scratch (device globals; allocation forbidden in kernel_launch)
// ---------------------------------------------------------------------------
__device__ __half g_qh[NQKV], g_ql[NQKV];
__device__ __half g_kh[NQKV], g_kl[NQKV];
__device__ __half g_vh[NQKV], g_vl[NQKV];
__device__ __half g_Wqh[EE * EE], g_Wql[EE * EE];
__device__ __half g_Wkh[EE * EE], g_Wkl[EE * EE];
__device__ __half g_Wvh[EE * EE], g_Wvl[EE * EE];
__device__ __half g_Qh[NQKV], g_Ql[NQKV];
__device__ __half g_Kh[NQKV], g_Kl[NQKV];
__device__ float  g_V[NQKV];
__device__ __half g_VTh[NQKV], g_VTl[NQKV];
__device__ float  g_S[NS];
__device__ __half g_Ph[NS], g_Pl[NS];

// ---------------------------------------------------------------------------
// Helpers
// ---------------------------------------------------------------------------
__device__ __forceinline__ uint32_t smem_u32(const void* p) {
    uint32_t a;
    asm("{ .reg .u64 t; cvta.to.shared.u64 t, %1; cvt.u32.u64 %0, t; }"
        : "=r"(a) : "l"(p));
    return a;
}

__device__ __forceinline__ void cp16(uint32_t dst_smem, const void* src_gmem) {
    asm volatile("cp.async.cg.shared.global [%0], [%1], 16;"
                 :: "r"(dst_smem), "l"(__cvta_generic_to_global(src_gmem)));
}
#define CP_COMMIT() asm volatile("cp.async.commit_group;" ::: "memory")
#define CP_WAIT1()  asm volatile("cp.async.wait_group 1;"  ::: "memory")

// ldmatrix x4 (non-transposed, b16)
__device__ __forceinline__ void ldsm4(uint32_t* r, uint32_t addr) {
    asm volatile("ldmatrix.sync.aligned.m8n8.x4.shared.b16 {%0,%1,%2,%3}, [%4];"
                 : "=r"(r[0]), "=r"(r[1]), "=r"(r[2]), "=r"(r[3]) : "r"(addr));
}

// m16n8k16 fp16 -> fp32 accumulate
__device__ __forceinline__ void mma16816(float* c,
                                         uint32_t a0, uint32_t a1, uint32_t a2, uint32_t a3,
                                         uint32_t b0, uint32_t b1) {
    asm volatile(
        "mma.sync.aligned.m16n8k16.row.col.f32.f16.f16.f32 "
        "{%0,%1,%2,%3}, {%4,%5,%6,%7}, {%8,%9}, {%0,%1,%2,%3};"
        : "+f"(c[0]), "+f"(c[1]), "+f"(c[2]), "+f"(c[3])
        : "r"(a0), "r"(a1), "r"(a2), "r"(a3), "r"(b0), "r"(b1));
}

// m16n8k16 fp16 -> fp16 accumulate (for small correction terms)
__device__ __forceinline__ void mma16816h(uint32_t* c,
                                          uint32_t a0, uint32_t a1, uint32_t a2, uint32_t a3,
                                          uint32_t b0, uint32_t b1) {
    asm volatile(
        "mma.sync.aligned.m16n8k16.row.col.f16.f16.f16.f16 "
        "{%0,%1}, {%2,%3,%4,%5}, {%6,%7}, {%0,%1};"
        : "+r"(c[0]), "+r"(c[1])
        : "r"(a0), "r"(a1), "r"(a2), "r"(a3), "r"(b0), "r"(b1));
}

__device__ __forceinline__ void split2(float x, __half& h, __half& l) {
    h = __float2half_rn(x);
    l = __float2half_rn(x - __half2float(h));
}

// ---------------------------------------------------------------------------
// Fused elementwise split: fp32 -> (hi, lo) fp16, 3 arrays per launch (z).
// ---------------------------------------------------------------------------
struct SplitArgs {
    const float* src[3];
    __half* hi[3];
    __half* lo[3];
    size_t n;
};

__global__ __launch_bounds__(256)
void split3_kernel(SplitArgs a)
{
    const int z = blockIdx.z;
    const float* __restrict__ x = a.src[z];
    __half* __restrict__ hi = a.hi[z];
    __half* __restrict__ lo = a.lo[z];
    const size_t n = a.n;
    const size_t stride = (size_t)gridDim.x * blockDim.x * 8;

    for (size_t i = ((size_t)blockIdx.x * blockDim.x + threadIdx.x) * 8;
         i < n; i += stride) {
#pragma unroll
        for (int w = 0; w < 2; w++) {
            float4 v = *(const float4*)(x + i + w * 4);
            __half h0, h1, h2, h3, l0, l1, l2, l3;
            split2(v.x, h0, l0); split2(v.y, h1, l1);
            split2(v.z, h2, l2); split2(v.w, h3, l3);
            __half2* ph = (__half2*)(hi + i + w * 4);
            __half2* pl = (__half2*)(lo + i + w * 4);
            ph[0] = __halves2half2(h0, h1);
            ph[1] = __halves2half2(h2, h3);
            pl[0] = __halves2half2(l0, l1);
            pl[1] = __halves2half2(l2, l3);
        }
    }
}

// ---------------------------------------------------------------------------
// Split-FP16 NT GEMM on tensor cores:
//   C[M,N] = alpha * (Ah+Al)[M,K] * (Bh+Bl)[N,K]^T
// Main term Ah*Bh in fp32-accum HMMA; corrections Ah*Bl + Al*Bh in
// fp16-accum HMMA, folded at epilogue.
// CTA: 128x128x32, 512 threads = 16 warps (4 x 4), warp tile 32x32.
// SMEM: 3 stages x 4 tiles (Ah, Al, Bh, Bl), each 128 rows x 80B.
// cp.async 3-deep pipeline; ONE __syncthreads per chunk.
// OUT_MODE 0: write fp32 C.  OUT_MODE 1: write split fp16 (Ch, Cl).
// Requires M%128==0, N%128==0, K%32==0.
// ---------------------------------------------------------------------------
#define SROW 80
#define TILE_B (128 * SROW)            // 10240
#define STAGE_B (4 * TILE_B)           // 40960
#define GEMM_SMEM (3 * STAGE_B)        // 122880

template <int OUT_MODE>
__global__ __launch_bounds__(512, 1)
void gemm_f16pair_nt(const __half* __restrict__ Ah, const __half* __restrict__ Al,
                     const __half* __restrict__ Bh, const __half* __restrict__ Bl,
                     float* __restrict__ C, __half* __restrict__ Ch,
                     __half* __restrict__ Cl,
                     int M, int N, int K, float alpha,
                     size_t sA, size_t sB, size_t sC)
{
    extern __shared__ __align__(128) char smem[];
    const uint32_t sb = smem_u32(smem);

    const int tid  = threadIdx.x;
    const int wid  = tid >> 5;
    const int lane = tid & 31;
    const int wm   = wid >> 2;          // 0..3
    const int wn   = wid & 3;           // 0..3
    const int g    = lane >> 2;         // 0..7
    const int i4   = lane & 3;          // 0..3

    const size_t z = blockIdx.z;
    const __half* pAh = Ah + z * sA;
    const __half* pAl = Al + z * sA;
    const __half* pBh = Bh + z * sB;
    const __half* pBl = Bl + z * sB;

    const int aRow0 = blockIdx.y * 128;
    const int bRow0 = blockIdx.x * 128;

    // cp.async copy indices: 512 threads -> 1 cp16 per tile per thread
    const int cr = tid >> 2;             // rows 0..127
    const int cq = tid & 3;              // 16B quarter 0..3

    // ldmatrix per-lane address offsets
    const int lmA = lane & 15;
    const int lqA = (lane >> 4) & 1;
    uint32_t aoff[2];
#pragma unroll
    for (int fm = 0; fm < 2; fm++)
        aoff[fm] = (uint32_t)((wm * 32 + fm * 16 + lmA) * SROW + lqA * 16);
    const int bn = (lane & 7) + ((lane >> 4) << 3);
    const int bq = (lane >> 3) & 1;
    uint32_t boff[2];
#pragma unroll
    for (int fp = 0; fp < 2; fp++)
        boff[fp] = (uint32_t)((wn * 32 + fp * 16 + bn) * SROW + bq * 16);

    float acc[2][4][4];
    uint32_t crr[2][4][2];
#pragma unroll
    for (int a = 0; a < 2; a++)
#pragma unroll
        for (int b = 0; b < 4; b++) {
#pragma unroll
            for (int c = 0; c < 4; c++) acc[a][b][c] = 0.0f;
            crr[a][b][0] = 0u; crr[a][b][1] = 0u;
        }

    const int nch = K >> 5;

    auto issue = [&](int kc) {
        const uint32_t tb = sb + (uint32_t)(kc % 3) * STAGE_B;
        const int kofs = kc << 5;
        const uint32_t so = (uint32_t)(cr * SROW + cq * 16);
        const size_t goA = (size_t)(aRow0 + cr) * K + kofs + cq * 8;
        const size_t goB = (size_t)(bRow0 + cr) * K + kofs + cq * 8;
        cp16(tb + 0 * TILE_B + so, pAh + goA);
        cp16(tb + 1 * TILE_B + so, pAl + goA);
        cp16(tb + 2 * TILE_B + so, pBh + goB);
        cp16(tb + 3 * TILE_B + so, pBl + goB);
        CP_COMMIT();
    };

    issue(0);
    issue(1);

    for (int kc = 0; kc < nch; kc++) {
        CP_WAIT1();
        __syncthreads();
        if (kc + 2 < nch) issue(kc + 2);

        const uint32_t tb = sb + (uint32_t)(kc % 3) * STAGE_B;
#pragma unroll
        for (int h = 0; h < 2; h++) {
            const uint32_t ho = (uint32_t)(h * 32);
            uint32_t ah[2][4], al[2][4];
#pragma unroll
            for (int fm = 0; fm < 2; fm++) {
                ldsm4(ah[fm], tb + 0 * TILE_B + aoff[fm] + ho);
                ldsm4(al[fm], tb + 1 * TILE_B + aoff[fm] + ho);
            }
            uint32_t bh[2][4], bl[2][4];
#pragma unroll
            for (int fp = 0; fp < 2; fp++) {
                ldsm4(bh[fp], tb + 2 * TILE_B + boff[fp] + ho);
                ldsm4(bl[fp], tb + 3 * TILE_B + boff[fp] + ho);
            }
#pragma unroll
            for (int fn = 0; fn < 4; fn++) {
                const uint32_t b0h = bh[fn >> 1][(fn & 1) * 2];
                const uint32_t b1h = bh[fn >> 1][(fn & 1) * 2 + 1];
                const uint32_t b0l = bl[fn >> 1][(fn & 1) * 2];
                const uint32_t b1l = bl[fn >> 1][(fn & 1) * 2 + 1];
#pragma unroll
                for (int fm = 0; fm < 2; fm++) {
                    mma16816(acc[fm][fn], ah[fm][0], ah[fm][1], ah[fm][2], ah[fm][3], b0h, b1h);
                    mma16816h(crr[fm][fn], ah[fm][0], ah[fm][1], ah[fm][2], ah[fm][3], b0l, b1l);
                    mma16816h(crr[fm][fn], al[fm][0], al[fm][1], al[fm][2], al[fm][3], b0h, b1h);
                }
            }
        }
    }

    // Epilogue: fold fp16 corrections into fp32 accumulators, scale, store
    const int rowB = aRow0 + wm * 32 + g;
    const int colB = bRow0 + wn * 32 + i4 * 2;
#pragma unroll
    for (int fm = 0; fm < 2; fm++) {
#pragma unroll
        for (int fn = 0; fn < 4; fn++) {
            const int row = rowB + fm * 16;
            const int col = colB + fn * 8;
            float2 k0 = __half22float2(*(__half2*)&crr[fm][fn][0]);
            float2 k1 = __half22float2(*(__half2*)&crr[fm][fn][1]);
            float c0 = alpha * (acc[fm][fn][0] + k0.x);
            float c1 = alpha * (acc[fm][fn][1] + k0.y);
            float c2 = alpha * (acc[fm][fn][2] + k1.x);
            float c3 = alpha * (acc[fm][fn][3] + k1.y);
            if (OUT_MODE == 0) {
                float* pc = C + z * sC;
                *(float2*)(pc + (size_t)row * N + col)       = make_float2(c0, c1);
                *(float2*)(pc + (size_t)(row + 8) * N + col) = make_float2(c2, c3);
            } else {
                __half* ph = Ch + z * sC;
                __half* pl = Cl + z * sC;
                __half h0, h1, h2, h3, l0, l1, l2, l3;
                split2(c0, h0, l0); split2(c1, h1, l1);
                split2(c2, h2, l2); split2(c3, h3, l3);
                *(__half2*)(ph + (size_t)row * N + col)       = __halves2half2(h0, h1);
                *(__half2*)(pl + (size_t)row * N + col)       = __halves2half2(l0, l1);
                *(__half2*)(ph + (size_t)(row + 8) * N + col) = __halves2half2(h2, h3);
                *(__half2*)(pl + (size_t)(row + 8) * N + col) = __halves2half2(l2, l3);
            }
        }
    }
}

// ---------------------------------------------------------------------------
// Transpose + split: V[b][s][o] fp32 -> VThi/VTlo[b][o][s] fp16
// ---------------------------------------------------------------------------
__global__ __launch_bounds__(256)
void transpose_split_kernel(const float* __restrict__ V,
                            __half* __restrict__ Th, __half* __restrict__ Tl)
{
    __shared__ float t[32][33];
    const int b  = blockIdx.z;
    const int s0 = blockIdx.x << 5;
    const int o0 = blockIdx.y << 5;
    const float* Vb = V + (size_t)b * TT * EE;
    __half* Thb = Th + (size_t)b * EE * TT;
    __half* Tlb = Tl + (size_t)b * EE * TT;
    const int tx = threadIdx.x & 31;
    const int ty = threadIdx.x >> 5;
#pragma unroll
    for (int i = 0; i < 4; i++)
        t[ty + 8 * i][tx] = Vb[(size_t)(s0 + ty + 8 * i) * EE + o0 + tx];
    __syncthreads();
#pragma unroll
    for (int i = 0; i < 4; i++) {
        float x = t[tx][ty + 8 * i];
        __half h, l;
        split2(x, h, l);
        const size_t off = (size_t)(o0 + ty + 8 * i) * TT + s0 + tx;
        Thb[off] = h;
        Tlb[off] = l;
    }
}

// ---------------------------------------------------------------------------
// Masked row softmax: S[B*T, T] fp32 -> split fp16 (Ph, Pl). mask 0 -> -inf.
// ---------------------------------------------------------------------------
__global__ __launch_bounds__(256)
void softmax_split_kernel(const float* __restrict__ S, const int* __restrict__ mask,
                          __half* __restrict__ Ph, __half* __restrict__ Pl)
{
    const int row = blockIdx.x;
    const int t   = row & (TT - 1);
    const float* Srow = S + (size_t)row * TT;
    const int* mrow = mask + (size_t)t * TT;
    const int tid = threadIdx.x;

    float v[8];
    float m = -CUDART_INF_F;
#pragma unroll
    for (int i = 0; i < 8; i++) {
        int s = tid + i * 256;
        float x = (mrow[s] != 0) ? Srow[s] : -CUDART_INF_F;
        v[i] = x;
        m = fmaxf(m, x);
    }

    __shared__ float red[256];
    red[tid] = m;
    __syncthreads();
    for (int off = 128; off > 0; off >>= 1) {
        if (tid < off) red[tid] = fmaxf(red[tid], red[tid + off]);
        __syncthreads();
    }
    m = red[0];
    __syncthreads();

    float sum = 0.0f;
#pragma unroll
    for (int i = 0; i < 8; i++) {
        float e = __expf(v[i] - m);
        v[i] = e;
        sum += e;
    }
    red[tid] = sum;
    __syncthreads();
    for (int off = 128; off > 0; off >>= 1) {
        if (tid < off) red[tid] += red[tid + off];
        __syncthreads();
    }
    const float inv = 1.0f / red[0];

    __half* Phr = Ph + (size_t)row * TT;
    __half* Plr = Pl + (size_t)row * TT;
#pragma unroll
    for (int i = 0; i < 8; i++) {
        float p = v[i] * inv;
        __half h, l;
        split2(p, h, l);
        Phr[tid + i * 256] = h;
        Plr[tid + i * 256] = l;
    }
}

// ---------------------------------------------------------------------------
// kernel_launch
// Launch order (ncu -s 5 -c 1 profiles launch #6 = scores GEMM):
//   1 split3(q,k,v)  2 split3(W)  3 projQ  4 projK  5 projV
//   6 scores GEMM    7 transpose  8 softmax  9 PV GEMM
// ---------------------------------------------------------------------------
extern "C" void kernel_launch(void* const* d_in, const int* in_sizes, int n_in,
                              void* d_out, int out_size)
{
    const float* q    = (const float*)d_in[0];
    const float* k    = (const float*)d_in[1];
    const float* v    = (const float*)d_in[2];
    const int*   mask = (const int*)  d_in[3];
    const float* Wq   = (const float*)d_in[4];
    const float* Wk   = (const float*)d_in[5];
    const float* Wv   = (const float*)d_in[6];
    float* out = (float*)d_out;

    __half *qh, *ql, *kh, *kl, *vh, *vl;
    __half *wqh, *wql, *wkh, *wkl, *wvh, *wvl;
    __half *Qh, *Ql, *Kh, *Kl, *VTh, *VTl, *Ph, *Pl;
    float *V, *S;
    cudaGetSymbolAddress((void**)&qh,  g_qh);  cudaGetSymbolAddress((void**)&ql,  g_ql);
    cudaGetSymbolAddress((void**)&kh,  g_kh);  cudaGetSymbolAddress((void**)&kl,  g_kl);
    cudaGetSymbolAddress((void**)&vh,  g_vh);  cudaGetSymbolAddress((void**)&vl,  g_vl);
    cudaGetSymbolAddress((void**)&wqh, g_Wqh); cudaGetSymbolAddress((void**)&wql, g_Wql);
    cudaGetSymbolAddress((void**)&wkh, g_Wkh); cudaGetSymbolAddress((void**)&wkl, g_Wkl);
    cudaGetSymbolAddress((void**)&wvh, g_Wvh); cudaGetSymbolAddress((void**)&wvl, g_Wvl);
    cudaGetSymbolAddress((void**)&Qh,  g_Qh);  cudaGetSymbolAddress((void**)&Ql,  g_Ql);
    cudaGetSymbolAddress((void**)&Kh,  g_Kh);  cudaGetSymbolAddress((void**)&Kl,  g_Kl);
    cudaGetSymbolAddress((void**)&VTh, g_VTh); cudaGetSymbolAddress((void**)&VTl, g_VTl);
    cudaGetSymbolAddress((void**)&Ph,  g_Ph);  cudaGetSymbolAddress((void**)&Pl,  g_Pl);
    cudaGetSymbolAddress((void**)&V,   g_V);
    cudaGetSymbolAddress((void**)&S,   g_S);

    cudaFuncSetAttribute(gemm_f16pair_nt<0>,
                         cudaFuncAttributeMaxDynamicSharedMemorySize, GEMM_SMEM);
    cudaFuncSetAttribute(gemm_f16pair_nt<1>,
                         cudaFuncAttributeMaxDynamicSharedMemorySize, GEMM_SMEM);

    const int M = BB * TT;                   // 16384
    const size_t strQKV = (size_t)TT * EE;
    const size_t strS   = (size_t)TT * TT;
    const size_t strVT  = (size_t)EE * TT;

    // 1) Split q,k,v inputs (fused, grid.z selects array)
    {
        SplitArgs a;
        a.src[0] = q;  a.src[1] = k;  a.src[2] = v;
        a.hi[0] = qh;  a.hi[1] = kh;  a.hi[2] = vh;
        a.lo[0] = ql;  a.lo[1] = kl;  a.lo[2] = vl;
        a.n = NQKV;
        dim3 gs((unsigned)(NQKV / (256 * 8)), 1, 3);
        split3_kernel<<<gs, 256>>>(a);
    }
    // 2) Split weights (fused)
    {
        SplitArgs a;
        a.src[0] = Wq;  a.src[1] = Wk;  a.src[2] = Wv;
        a.hi[0] = wqh;  a.hi[1] = wkh;  a.hi[2] = wvh;
        a.lo[0] = wql;  a.lo[1] = wkl;  a.lo[2] = wvl;
        a.n = (size_t)EE * EE;
        dim3 gs((unsigned)((size_t)EE * EE / (256 * 8)), 1, 3);
        split3_kernel<<<gs, 256>>>(a);
    }

    // 3-5) Projections (M=16384, N=1024, K=1024)
    dim3 gProj(EE / 128, M / 128, 1);
    gemm_f16pair_nt<1><<<gProj, 512, GEMM_SMEM>>>(qh, ql, wqh, wql,
        nullptr, Qh, Ql, M, EE, EE, 1.0f, 0, 0, 0);
    gemm_f16pair_nt<1><<<gProj, 512, GEMM_SMEM>>>(kh, kl, wkh, wkl,
        nullptr, Kh, Kl, M, EE, EE, 1.0f, 0, 0, 0);
    gemm_f16pair_nt<0><<<gProj, 512, GEMM_SMEM>>>(vh, vl, wvh, wvl,
        V, nullptr, nullptr, M, EE, EE, 1.0f, 0, 0, 0);

    // 6) Scores: S_b = (Q_b K_b^T) / 32   (M=N=2048, K=1024, batched)
    dim3 gScore(TT / 128, TT / 128, BB);
    gemm_f16pair_nt<0><<<gScore, 512, GEMM_SMEM>>>(Qh, Ql, Kh, Kl,
        S, nullptr, nullptr, TT, TT, EE, 1.0f / 32.0f, strQKV, strQKV, strS);

    // 7) Transpose + split V -> VT (only needed before PV)
    dim3 gT(TT / 32, EE / 32, BB);
    transpose_split_kernel<<<gT, 256>>>(V, VTh, VTl);

    // 8) Masked softmax -> split fp16 P
    softmax_split_kernel<<<BB * TT, 256>>>(S, mask, Ph, Pl);

    // 9) Output: O_b = P_b VT_b^T  (M=2048, N=1024, K=2048, batched)
    dim3 gOut(EE / 128, TT / 128, BB);
    gemm_f16pair_nt<0><<<gOut, 512, GEMM_SMEM>>>(Ph, Pl, VTh, VTl,
        out, nullptr, nullptr, TT, EE, TT, 1.0f, strS, strVT, strQKV);
}

// round 7
// speedup vs baseline: 1.3001x; 1.2907x over previous
#include <cuda_runtime.h>
#include <cuda_fp16.h>
#include <math_constants.h>
#include <cstdint>

// Problem constants
#define BB 8
#define TT 2048
#define EE 1024
#define NQKV ((size_t)BB * TT * EE)   // 16,777,216
#define NS   ((size_t)BB * TT * TT)   // 33,554,432

// ---------------------------------------------------------------------------
// Scratch (device globals; allocation forbidden in kernel_launch)
// A-side operands need (hi, lo); B-side operands need hi only (2-pass scheme).
// ---------------------------------------------------------------------------
__device__ __half g_qh[NQKV], g_ql[NQKV];       // q input (A in projQ)
__device__ __half g_kh[NQKV], g_kl[NQKV];       // k input (A in projK)
__device__ __half g_vh[NQKV], g_vl[NQKV];       // v input (A in projV)
__device__ __half g_Wqh[EE * EE];               // weights (B side, hi only)
__device__ __half g_Wkh[EE * EE];
__device__ __half g_Wvh[EE * EE];
__device__ __half g_Qh[NQKV], g_Ql[NQKV];       // Q (A in scores)
__device__ __half g_Kh[NQKV];                   // K (B in scores, hi only)
__device__ __half g_Vh[NQKV];                   // V projected (hi only)
__device__ __half g_VTh[NQKV];                  // V transposed (B in PV)
__device__ float  g_S[NS];                      // scores
__device__ __half g_Ph[NS], g_Pl[NS];           // softmax weights (A in PV)

// ---------------------------------------------------------------------------
// Helpers
// ---------------------------------------------------------------------------
__device__ __forceinline__ uint32_t smem_u32(const void* p) {
    uint32_t a;
    asm("{ .reg .u64 t; cvta.to.shared.u64 t, %1; cvt.u32.u64 %0, t; }"
        : "=r"(a) : "l"(p));
    return a;
}

__device__ __forceinline__ void cp16(uint32_t dst_smem, const void* src_gmem) {
    asm volatile("cp.async.cg.shared.global [%0], [%1], 16;"
                 :: "r"(dst_smem), "l"(__cvta_generic_to_global(src_gmem)));
}
#define CP_COMMIT() asm volatile("cp.async.commit_group;" ::: "memory")
#define CP_WAIT1()  asm volatile("cp.async.wait_group 1;"  ::: "memory")

// ldmatrix x4 (non-transposed, b16)
__device__ __forceinline__ void ldsm4(uint32_t* r, uint32_t addr) {
    asm volatile("ldmatrix.sync.aligned.m8n8.x4.shared.b16 {%0,%1,%2,%3}, [%4];"
                 : "=r"(r[0]), "=r"(r[1]), "=r"(r[2]), "=r"(r[3]) : "r"(addr));
}

// m16n8k16 fp16 -> fp32 accumulate
__device__ __forceinline__ void mma16816(float* c,
                                         uint32_t a0, uint32_t a1, uint32_t a2, uint32_t a3,
                                         uint32_t b0, uint32_t b1) {
    asm volatile(
        "mma.sync.aligned.m16n8k16.row.col.f32.f16.f16.f32 "
        "{%0,%1,%2,%3}, {%4,%5,%6,%7}, {%8,%9}, {%0,%1,%2,%3};"
        : "+f"(c[0]), "+f"(c[1]), "+f"(c[2]), "+f"(c[3])
        : "r"(a0), "r"(a1), "r"(a2), "r"(a3), "r"(b0), "r"(b1));
}

// m16n8k16 fp16 -> fp16 accumulate (small correction term)
__device__ __forceinline__ void mma16816h(uint32_t* c,
                                          uint32_t a0, uint32_t a1, uint32_t a2, uint32_t a3,
                                          uint32_t b0, uint32_t b1) {
    asm volatile(
        "mma.sync.aligned.m16n8k16.row.col.f16.f16.f16.f16 "
        "{%0,%1}, {%2,%3,%4,%5}, {%6,%7}, {%0,%1};"
        : "+r"(c[0]), "+r"(c[1])
        : "r"(a0), "r"(a1), "r"(a2), "r"(a3), "r"(b0), "r"(b1));
}

__device__ __forceinline__ void split2(float x, __half& h, __half& l) {
    h = __float2half_rn(x);
    l = __float2half_rn(x - __half2float(h));
}

// ---------------------------------------------------------------------------
// Fused elementwise split: fp32 -> (hi, lo) fp16, 3 arrays per launch (z).
// ---------------------------------------------------------------------------
struct SplitArgs {
    const float* src[3];
    __half* hi[3];
    __half* lo[3];
    size_t n;
};

__global__ __launch_bounds__(256)
void split3_kernel(SplitArgs a)
{
    const int z = blockIdx.z;
    const float* __restrict__ x = a.src[z];
    __half* __restrict__ hi = a.hi[z];
    __half* __restrict__ lo = a.lo[z];
    const size_t n = a.n;
    const size_t stride = (size_t)gridDim.x * blockDim.x * 8;

    for (size_t i = ((size_t)blockIdx.x * blockDim.x + threadIdx.x) * 8;
         i < n; i += stride) {
#pragma unroll
        for (int w = 0; w < 2; w++) {
            float4 v = *(const float4*)(x + i + w * 4);
            __half h0, h1, h2, h3, l0, l1, l2, l3;
            split2(v.x, h0, l0); split2(v.y, h1, l1);
            split2(v.z, h2, l2); split2(v.w, h3, l3);
            __half2* ph = (__half2*)(hi + i + w * 4);
            __half2* pl = (__half2*)(lo + i + w * 4);
            ph[0] = __halves2half2(h0, h1);
            ph[1] = __halves2half2(h2, h3);
            pl[0] = __halves2half2(l0, l1);
            pl[1] = __halves2half2(l2, l3);
        }
    }
}

// ---------------------------------------------------------------------------
// Fused convert: fp32 -> fp16 (hi only), 3 arrays per launch (z).
// ---------------------------------------------------------------------------
struct CvtArgs {
    const float* src[3];
    __half* dst[3];
    size_t n;
};

__global__ __launch_bounds__(256)
void convert3_kernel(CvtArgs a)
{
    const int z = blockIdx.z;
    const float* __restrict__ x = a.src[z];
    __half* __restrict__ d = a.dst[z];
    const size_t n = a.n;
    const size_t stride = (size_t)gridDim.x * blockDim.x * 8;

    for (size_t i = ((size_t)blockIdx.x * blockDim.x + threadIdx.x) * 8;
         i < n; i += stride) {
#pragma unroll
        for (int w = 0; w < 2; w++) {
            float4 v = *(const float4*)(x + i + w * 4);
            __half2* pd = (__half2*)(d + i + w * 4);
            pd[0] = __halves2half2(__float2half_rn(v.x), __float2half_rn(v.y));
            pd[1] = __halves2half2(__float2half_rn(v.z), __float2half_rn(v.w));
        }
    }
}

// ---------------------------------------------------------------------------
// 2-pass split-FP16 NT GEMM on tensor cores:
//   C[M,N] ~= alpha * ((Ah+Al)[M,K]) * Bh[N,K]^T
// Main Ah*Bh fp32-acc; correction Al*Bh fp16-acc, folded at epilogue.
// CTA: 128x128x32, 512 threads = 16 warps (4x4), warp tile 32x32.
// SMEM: 3 stages x 3 tiles (Ah, Al, Bh), each 128 rows x 80B.
// OUT_MODE 0: fp32 C.  1: split fp16 (Ch, Cl).  2: fp16 hi only (Ch).
// Requires M%128==0, N%128==0, K%32==0.
// ---------------------------------------------------------------------------
#define SROW 80
#define TILE_B (128 * SROW)            // 10240
#define STAGE_B (3 * TILE_B)           // 30720
#define GEMM_SMEM (3 * STAGE_B)        // 92160

template <int OUT_MODE>
__global__ __launch_bounds__(512, 1)
void gemm_f16pair_nt(const __half* __restrict__ Ah, const __half* __restrict__ Al,
                     const __half* __restrict__ Bh,
                     float* __restrict__ C, __half* __restrict__ Ch,
                     __half* __restrict__ Cl,
                     int M, int N, int K, float alpha,
                     size_t sA, size_t sB, size_t sC)
{
    extern __shared__ __align__(128) char smem[];
    const uint32_t sb = smem_u32(smem);

    const int tid  = threadIdx.x;
    const int wid  = tid >> 5;
    const int lane = tid & 31;
    const int wm   = wid >> 2;          // 0..3
    const int wn   = wid & 3;           // 0..3
    const int g    = lane >> 2;         // 0..7
    const int i4   = lane & 3;          // 0..3

    const size_t z = blockIdx.z;
    const __half* pAh = Ah + z * sA;
    const __half* pAl = Al + z * sA;
    const __half* pBh = Bh + z * sB;

    const int aRow0 = blockIdx.y * 128;
    const int bRow0 = blockIdx.x * 128;

    // cp.async copy indices: 512 threads -> 1 cp16 per tile per thread
    const int cr = tid >> 2;             // rows 0..127
    const int cq = tid & 3;              // 16B quarter 0..3

    // ldmatrix per-lane address offsets
    const int lmA = lane & 15;
    const int lqA = (lane >> 4) & 1;
    uint32_t aoff[2];
#pragma unroll
    for (int fm = 0; fm < 2; fm++)
        aoff[fm] = (uint32_t)((wm * 32 + fm * 16 + lmA) * SROW + lqA * 16);
    const int bn = (lane & 7) + ((lane >> 4) << 3);
    const int bq = (lane >> 3) & 1;
    uint32_t boff[2];
#pragma unroll
    for (int fp = 0; fp < 2; fp++)
        boff[fp] = (uint32_t)((wn * 32 + fp * 16 + bn) * SROW + bq * 16);

    float acc[2][4][4];
    uint32_t crr[2][4][2];
#pragma unroll
    for (int a = 0; a < 2; a++)
#pragma unroll
        for (int b = 0; b < 4; b++) {
#pragma unroll
            for (int c = 0; c < 4; c++) acc[a][b][c] = 0.0f;
            crr[a][b][0] = 0u; crr[a][b][1] = 0u;
        }

    const int nch = K >> 5;

    auto issue = [&](int kc) {
        const uint32_t tb = sb + (uint32_t)(kc % 3) * STAGE_B;
        const int kofs = kc << 5;
        const uint32_t so = (uint32_t)(cr * SROW + cq * 16);
        const size_t goA = (size_t)(aRow0 + cr) * K + kofs + cq * 8;
        const size_t goB = (size_t)(bRow0 + cr) * K + kofs + cq * 8;
        cp16(tb + 0 * TILE_B + so, pAh + goA);
        cp16(tb + 1 * TILE_B + so, pAl + goA);
        cp16(tb + 2 * TILE_B + so, pBh + goB);
        CP_COMMIT();
    };

    issue(0);
    issue(1);

    for (int kc = 0; kc < nch; kc++) {
        CP_WAIT1();
        __syncthreads();
        if (kc + 2 < nch) issue(kc + 2);

        const uint32_t tb = sb + (uint32_t)(kc % 3) * STAGE_B;
#pragma unroll
        for (int h = 0; h < 2; h++) {
            const uint32_t ho = (uint32_t)(h * 32);
            uint32_t ah[2][4], al[2][4];
#pragma unroll
            for (int fm = 0; fm < 2; fm++) {
                ldsm4(ah[fm], tb + 0 * TILE_B + aoff[fm] + ho);
                ldsm4(al[fm], tb + 1 * TILE_B + aoff[fm] + ho);
            }
            uint32_t bh[2][4];
#pragma unroll
            for (int fp = 0; fp < 2; fp++)
                ldsm4(bh[fp], tb + 2 * TILE_B + boff[fp] + ho);
#pragma unroll
            for (int fn = 0; fn < 4; fn++) {
                const uint32_t b0h = bh[fn >> 1][(fn & 1) * 2];
                const uint32_t b1h = bh[fn >> 1][(fn & 1) * 2 + 1];
#pragma unroll
                for (int fm = 0; fm < 2; fm++) {
                    mma16816(acc[fm][fn], ah[fm][0], ah[fm][1], ah[fm][2], ah[fm][3], b0h, b1h);
                    mma16816h(crr[fm][fn], al[fm][0], al[fm][1], al[fm][2], al[fm][3], b0h, b1h);
                }
            }
        }
    }

    // Epilogue: fold fp16 correction into fp32 accumulators, scale, store
    const int rowB = aRow0 + wm * 32 + g;
    const int colB = bRow0 + wn * 32 + i4 * 2;
#pragma unroll
    for (int fm = 0; fm < 2; fm++) {
#pragma unroll
        for (int fn = 0; fn < 4; fn++) {
            const int row = rowB + fm * 16;
            const int col = colB + fn * 8;
            float2 k0 = __half22float2(*(__half2*)&crr[fm][fn][0]);
            float2 k1 = __half22float2(*(__half2*)&crr[fm][fn][1]);
            float c0 = alpha * (acc[fm][fn][0] + k0.x);
            float c1 = alpha * (acc[fm][fn][1] + k0.y);
            float c2 = alpha * (acc[fm][fn][2] + k1.x);
            float c3 = alpha * (acc[fm][fn][3] + k1.y);
            if (OUT_MODE == 0) {
                float* pc = C + z * sC;
                *(float2*)(pc + (size_t)row * N + col)       = make_float2(c0, c1);
                *(float2*)(pc + (size_t)(row + 8) * N + col) = make_float2(c2, c3);
            } else if (OUT_MODE == 1) {
                __half* ph = Ch + z * sC;
                __half* pl = Cl + z * sC;
                __half h0, h1, h2, h3, l0, l1, l2, l3;
                split2(c0, h0, l0); split2(c1, h1, l1);
                split2(c2, h2, l2); split2(c3, h3, l3);
                *(__half2*)(ph + (size_t)row * N + col)       = __halves2half2(h0, h1);
                *(__half2*)(pl + (size_t)row * N + col)       = __halves2half2(l0, l1);
                *(__half2*)(ph + (size_t)(row + 8) * N + col) = __halves2half2(h2, h3);
                *(__half2*)(pl + (size_t)(row + 8) * N + col) = __halves2half2(l2, l3);
            } else {
                __half* ph = Ch + z * sC;
                *(__half2*)(ph + (size_t)row * N + col) =
                    __halves2half2(__float2half_rn(c0), __float2half_rn(c1));
                *(__half2*)(ph + (size_t)(row + 8) * N + col) =
                    __halves2half2(__float2half_rn(c2), __float2half_rn(c3));
            }
        }
    }
}

// ---------------------------------------------------------------------------
// Transpose fp16: V[b][s][o] -> VT[b][o][s] (32x32 tiles)
// ---------------------------------------------------------------------------
__global__ __launch_bounds__(256)
void transpose_h_kernel(const __half* __restrict__ V, __half* __restrict__ T)
{
    __shared__ uint16_t t[32][34];   // 68B row stride -> conflict-free columns
    const int b  = blockIdx.z;
    const int s0 = blockIdx.x << 5;
    const int o0 = blockIdx.y << 5;
    const __half* Vb = V + (size_t)b * TT * EE;
    __half* Tb = T + (size_t)b * EE * TT;
    const int tx = threadIdx.x & 31;
    const int ty = threadIdx.x >> 5;
#pragma unroll
    for (int i = 0; i < 4; i++)
        t[ty + 8 * i][tx] = __half_as_ushort(Vb[(size_t)(s0 + ty + 8 * i) * EE + o0 + tx]);
    __syncthreads();
#pragma unroll
    for (int i = 0; i < 4; i++)
        Tb[(size_t)(o0 + ty + 8 * i) * TT + s0 + tx] = __ushort_as_half(t[tx][ty + 8 * i]);
}

// ---------------------------------------------------------------------------
// Masked row softmax: S[B*T, T] fp32 -> split fp16 (Ph, Pl). mask 0 -> -inf.
// ---------------------------------------------------------------------------
__global__ __launch_bounds__(256)
void softmax_split_kernel(const float* __restrict__ S, const int* __restrict__ mask,
                          __half* __restrict__ Ph, __half* __restrict__ Pl)
{
    const int row = blockIdx.x;
    const int t   = row & (TT - 1);
    const float* Srow = S + (size_t)row * TT;
    const int* mrow = mask + (size_t)t * TT;
    const int tid = threadIdx.x;

    float v[8];
    float m = -CUDART_INF_F;
#pragma unroll
    for (int i = 0; i < 8; i++) {
        int s = tid + i * 256;
        float x = (mrow[s] != 0) ? Srow[s] : -CUDART_INF_F;
        v[i] = x;
        m = fmaxf(m, x);
    }

    __shared__ float red[256];
    red[tid] = m;
    __syncthreads();
    for (int off = 128; off > 0; off >>= 1) {
        if (tid < off) red[tid] = fmaxf(red[tid], red[tid + off]);
        __syncthreads();
    }
    m = red[0];
    __syncthreads();

    float sum = 0.0f;
#pragma unroll
    for (int i = 0; i < 8; i++) {
        float e = __expf(v[i] - m);
        v[i] = e;
        sum += e;
    }
    red[tid] = sum;
    __syncthreads();
    for (int off = 128; off > 0; off >>= 1) {
        if (tid < off) red[tid] += red[tid + off];
        __syncthreads();
    }
    const float inv = 1.0f / red[0];

    __half* Phr = Ph + (size_t)row * TT;
    __half* Plr = Pl + (size_t)row * TT;
#pragma unroll
    for (int i = 0; i < 8; i++) {
        float p = v[i] * inv;
        __half h, l;
        split2(p, h, l);
        Phr[tid + i * 256] = h;
        Plr[tid + i * 256] = l;
    }
}

// ---------------------------------------------------------------------------
// kernel_launch
// Order: 1 split3(q,k,v)  2 convert3(W)  3 projQ  4 projK  5 projV
//        6 scores GEMM    7 transpose    8 softmax  9 PV GEMM
// ---------------------------------------------------------------------------
extern "C" void kernel_launch(void* const* d_in, const int* in_sizes, int n_in,
                              void* d_out, int out_size)
{
    const float* q    = (const float*)d_in[0];
    const float* k    = (const float*)d_in[1];
    const float* v    = (const float*)d_in[2];
    const int*   mask = (const int*)  d_in[3];
    const float* Wq   = (const float*)d_in[4];
    const float* Wk   = (const float*)d_in[5];
    const float* Wv   = (const float*)d_in[6];
    float* out = (float*)d_out;

    __half *qh, *ql, *kh, *kl, *vh, *vl;
    __half *wqh, *wkh, *wvh;
    __half *Qh, *Ql, *Kh, *Vh, *VTh, *Ph, *Pl;
    float *S;
    cudaGetSymbolAddress((void**)&qh,  g_qh);  cudaGetSymbolAddress((void**)&ql,  g_ql);
    cudaGetSymbolAddress((void**)&kh,  g_kh);  cudaGetSymbolAddress((void**)&kl,  g_kl);
    cudaGetSymbolAddress((void**)&vh,  g_vh);  cudaGetSymbolAddress((void**)&vl,  g_vl);
    cudaGetSymbolAddress((void**)&wqh, g_Wqh);
    cudaGetSymbolAddress((void**)&wkh, g_Wkh);
    cudaGetSymbolAddress((void**)&wvh, g_Wvh);
    cudaGetSymbolAddress((void**)&Qh,  g_Qh);  cudaGetSymbolAddress((void**)&Ql,  g_Ql);
    cudaGetSymbolAddress((void**)&Kh,  g_Kh);
    cudaGetSymbolAddress((void**)&Vh,  g_Vh);
    cudaGetSymbolAddress((void**)&VTh, g_VTh);
    cudaGetSymbolAddress((void**)&Ph,  g_Ph);  cudaGetSymbolAddress((void**)&Pl,  g_Pl);
    cudaGetSymbolAddress((void**)&S,   g_S);

    cudaFuncSetAttribute(gemm_f16pair_nt<0>,
                         cudaFuncAttributeMaxDynamicSharedMemorySize, GEMM_SMEM);
    cudaFuncSetAttribute(gemm_f16pair_nt<1>,
                         cudaFuncAttributeMaxDynamicSharedMemorySize, GEMM_SMEM);
    cudaFuncSetAttribute(gemm_f16pair_nt<2>,
                         cudaFuncAttributeMaxDynamicSharedMemorySize, GEMM_SMEM);

    const int M = BB * TT;                   // 16384
    const size_t strQKV = (size_t)TT * EE;
    const size_t strS   = (size_t)TT * TT;
    const size_t strVT  = (size_t)EE * TT;

    // 1) Split q,k,v inputs (A-side: hi+lo)
    {
        SplitArgs a;
        a.src[0] = q;  a.src[1] = k;  a.src[2] = v;
        a.hi[0] = qh;  a.hi[1] = kh;  a.hi[2] = vh;
        a.lo[0] = ql;  a.lo[1] = kl;  a.lo[2] = vl;
        a.n = NQKV;
        dim3 gs((unsigned)(NQKV / (256 * 8)), 1, 3);
        split3_kernel<<<gs, 256>>>(a);
    }
    // 2) Convert weights (B-side: hi only)
    {
        CvtArgs a;
        a.src[0] = Wq;  a.src[1] = Wk;  a.src[2] = Wv;
        a.dst[0] = wqh; a.dst[1] = wkh; a.dst[2] = wvh;
        a.n = (size_t)EE * EE;
        dim3 gs((unsigned)((size_t)EE * EE / (256 * 8)), 1, 3);
        convert3_kernel<<<gs, 256>>>(a);
    }

    // 3-5) Projections (M=16384, N=1024, K=1024)
    dim3 gProj(EE / 128, M / 128, 1);
    // Q = q @ Wq^T -> split hi+lo (A in scores)
    gemm_f16pair_nt<1><<<gProj, 512, GEMM_SMEM>>>(qh, ql, wqh,
        nullptr, Qh, Ql, M, EE, EE, 1.0f, 0, 0, 0);
    // K = k @ Wk^T -> hi only (B in scores)
    gemm_f16pair_nt<2><<<gProj, 512, GEMM_SMEM>>>(kh, kl, wkh,
        nullptr, Kh, nullptr, M, EE, EE, 1.0f, 0, 0, 0);
    // V = v @ Wv^T -> hi only (B in PV after transpose)
    gemm_f16pair_nt<2><<<gProj, 512, GEMM_SMEM>>>(vh, vl, wvh,
        nullptr, Vh, nullptr, M, EE, EE, 1.0f, 0, 0, 0);

    // 6) Scores: S_b = (Q_b K_b^T) / 32   (M=N=2048, K=1024, batched)
    dim3 gScore(TT / 128, TT / 128, BB);
    gemm_f16pair_nt<0><<<gScore, 512, GEMM_SMEM>>>(Qh, Ql, Kh,
        S, nullptr, nullptr, TT, TT, EE, 1.0f / 32.0f, strQKV, strQKV, strS);

    // 7) Transpose V (fp16) -> VT
    dim3 gT(TT / 32, EE / 32, BB);
    transpose_h_kernel<<<gT, 256>>>(Vh, VTh);

    // 8) Masked softmax -> split fp16 P (A in PV)
    softmax_split_kernel<<<BB * TT, 256>>>(S, mask, Ph, Pl);

    // 9) Output: O_b = P_b VT_b^T  (M=2048, N=1024, K=2048, batched)
    dim3 gOut(EE / 128, TT / 128, BB);
    gemm_f16pair_nt<0><<<gOut, 512, GEMM_SMEM>>>(Ph, Pl, VTh,
        out, nullptr, nullptr, TT, EE, TT, 1.0f, strS, strVT, strQKV);
}

// round 8
// speedup vs baseline: 1.6603x; 1.2770x over previous
#include <cuda_runtime.h>
#include <cuda_fp16.h>
#include <math_constants.h>
#include <cstdint>

// Problem constants
#define BB 8
#define TT 2048
#define EE 1024
#define NQKV ((size_t)BB * TT * EE)   // 16,777,216
#define NS   ((size_t)BB * TT * TT)   // 33,554,432

// ---------------------------------------------------------------------------
// Scratch (device globals; allocation forbidden in kernel_launch)
// ---------------------------------------------------------------------------
__device__ __half g_qh[NQKV], g_ql[NQKV];       // q input (A in projQ)
__device__ __half g_kh[NQKV], g_kl[NQKV];       // k input (A in projK)
__device__ __half g_vh[NQKV], g_vl[NQKV];       // v input (A in projV)
__device__ __half g_Wqh[EE * EE];               // weights (B side, hi only)
__device__ __half g_Wkh[EE * EE];
__device__ __half g_Wvh[EE * EE];
__device__ __half g_Qh[NQKV], g_Ql[NQKV];       // Q (A in scores, hi+lo)
__device__ __half g_Kh[NQKV];                   // K (B in scores)
__device__ __half g_Vh[NQKV];                   // V projected
__device__ __half g_VTh[NQKV];                  // V transposed (B in PV)
__device__ float  g_S[NS];                      // scores
__device__ __half g_Ph[NS];                     // softmax weights (A in PV, 1-pass)

// ---------------------------------------------------------------------------
// Helpers
// ---------------------------------------------------------------------------
__device__ __forceinline__ uint32_t smem_u32(const void* p) {
    uint32_t a;
    asm("{ .reg .u64 t; cvta.to.shared.u64 t, %1; cvt.u32.u64 %0, t; }"
        : "=r"(a) : "l"(p));
    return a;
}

__device__ __forceinline__ void cp16(uint32_t dst_smem, const void* src_gmem) {
    asm volatile("cp.async.cg.shared.global [%0], [%1], 16;"
                 :: "r"(dst_smem), "l"(__cvta_generic_to_global(src_gmem)));
}
#define CP_COMMIT() asm volatile("cp.async.commit_group;" ::: "memory")
#define CP_WAIT1()  asm volatile("cp.async.wait_group 1;"  ::: "memory")

// ldmatrix x4 (non-transposed, b16)
__device__ __forceinline__ void ldsm4(uint32_t* r, uint32_t addr) {
    asm volatile("ldmatrix.sync.aligned.m8n8.x4.shared.b16 {%0,%1,%2,%3}, [%4];"
                 : "=r"(r[0]), "=r"(r[1]), "=r"(r[2]), "=r"(r[3]) : "r"(addr));
}

// m16n8k16 fp16 -> fp32 accumulate
__device__ __forceinline__ void mma16816(float* c,
                                         uint32_t a0, uint32_t a1, uint32_t a2, uint32_t a3,
                                         uint32_t b0, uint32_t b1) {
    asm volatile(
        "mma.sync.aligned.m16n8k16.row.col.f32.f16.f16.f32 "
        "{%0,%1,%2,%3}, {%4,%5,%6,%7}, {%8,%9}, {%0,%1,%2,%3};"
        : "+f"(c[0]), "+f"(c[1]), "+f"(c[2]), "+f"(c[3])
        : "r"(a0), "r"(a1), "r"(a2), "r"(a3), "r"(b0), "r"(b1));
}

// m16n8k16 fp16 -> fp16 accumulate (small correction term)
__device__ __forceinline__ void mma16816h(uint32_t* c,
                                          uint32_t a0, uint32_t a1, uint32_t a2, uint32_t a3,
                                          uint32_t b0, uint32_t b1) {
    asm volatile(
        "mma.sync.aligned.m16n8k16.row.col.f16.f16.f16.f16 "
        "{%0,%1}, {%2,%3,%4,%5}, {%6,%7}, {%0,%1};"
        : "+r"(c[0]), "+r"(c[1])
        : "r"(a0), "r"(a1), "r"(a2), "r"(a3), "r"(b0), "r"(b1));
}

__device__ __forceinline__ void split2(float x, __half& h, __half& l) {
    h = __float2half_rn(x);
    l = __float2half_rn(x - __half2float(h));
}

// ---------------------------------------------------------------------------
// Fused elementwise split: fp32 -> (hi, lo) fp16, 3 arrays per launch (z).
// ---------------------------------------------------------------------------
struct SplitArgs {
    const float* src[3];
    __half* hi[3];
    __half* lo[3];
    size_t n;
};

__global__ __launch_bounds__(256)
void split3_kernel(SplitArgs a)
{
    const int z = blockIdx.z;
    const float* __restrict__ x = a.src[z];
    __half* __restrict__ hi = a.hi[z];
    __half* __restrict__ lo = a.lo[z];
    const size_t n = a.n;
    const size_t stride = (size_t)gridDim.x * blockDim.x * 8;

    for (size_t i = ((size_t)blockIdx.x * blockDim.x + threadIdx.x) * 8;
         i < n; i += stride) {
#pragma unroll
        for (int w = 0; w < 2; w++) {
            float4 v = *(const float4*)(x + i + w * 4);
            __half h0, h1, h2, h3, l0, l1, l2, l3;
            split2(v.x, h0, l0); split2(v.y, h1, l1);
            split2(v.z, h2, l2); split2(v.w, h3, l3);
            __half2* ph = (__half2*)(hi + i + w * 4);
            __half2* pl = (__half2*)(lo + i + w * 4);
            ph[0] = __halves2half2(h0, h1);
            ph[1] = __halves2half2(h2, h3);
            pl[0] = __halves2half2(l0, l1);
            pl[1] = __halves2half2(l2, l3);
        }
    }
}

// ---------------------------------------------------------------------------
// Fused convert: fp32 -> fp16 (hi only), 3 arrays per launch (z).
// ---------------------------------------------------------------------------
struct CvtArgs {
    const float* src[3];
    __half* dst[3];
    size_t n;
};

__global__ __launch_bounds__(256)
void convert3_kernel(CvtArgs a)
{
    const int z = blockIdx.z;
    const float* __restrict__ x = a.src[z];
    __half* __restrict__ d = a.dst[z];
    const size_t n = a.n;
    const size_t stride = (size_t)gridDim.x * blockDim.x * 8;

    for (size_t i = ((size_t)blockIdx.x * blockDim.x + threadIdx.x) * 8;
         i < n; i += stride) {
#pragma unroll
        for (int w = 0; w < 2; w++) {
            float4 v = *(const float4*)(x + i + w * 4);
            __half2* pd = (__half2*)(d + i + w * 4);
            pd[0] = __halves2half2(__float2half_rn(v.x), __float2half_rn(v.y));
            pd[1] = __halves2half2(__float2half_rn(v.z), __float2half_rn(v.w));
        }
    }
}

// ---------------------------------------------------------------------------
// Split-FP16 NT GEMM on tensor cores, K-chunk 64:
//   TWOPASS=1: C ~= alpha * ((Ah+Al) * Bh^T)   (main fp32-acc + corr fp16-acc)
//   TWOPASS=0: C  = alpha * (Ah * Bh^T)        (single pass)
// CTA: 128x128x64, 512 threads = 16 warps (4x4), warp tile 32x32.
// SMEM: 3 stages x 3 tiles (Ah, Al, Bh), each 128 rows x 144B (128B data).
// OUT_MODE 0: fp32 C.  1: split fp16 (Ch, Cl).  2: fp16 hi only (Ch).
// Requires M%128==0, N%128==0, K%64==0.
// ---------------------------------------------------------------------------
#define SROW 144
#define TILE_B (128 * SROW)            // 18432
#define STAGE_B (3 * TILE_B)           // 55296
#define GEMM_SMEM (3 * STAGE_B)        // 165888

template <int OUT_MODE, int TWOPASS>
__global__ __launch_bounds__(512, 1)
void gemm_f16pair_nt(const __half* __restrict__ Ah, const __half* __restrict__ Al,
                     const __half* __restrict__ Bh,
                     float* __restrict__ C, __half* __restrict__ Ch,
                     __half* __restrict__ Cl,
                     int M, int N, int K, float alpha,
                     size_t sA, size_t sB, size_t sC)
{
    extern __shared__ __align__(128) char smem[];
    const uint32_t sb = smem_u32(smem);

    const int tid  = threadIdx.x;
    const int wid  = tid >> 5;
    const int lane = tid & 31;
    const int wm   = wid >> 2;          // 0..3
    const int wn   = wid & 3;           // 0..3
    const int g    = lane >> 2;         // 0..7
    const int i4   = lane & 3;          // 0..3

    const size_t z = blockIdx.z;
    const __half* pAh = Ah + z * sA;
    const __half* pAl = TWOPASS ? (Al + z * sA) : nullptr;
    const __half* pBh = Bh + z * sB;

    const int aRow0 = blockIdx.y * 128;
    const int bRow0 = blockIdx.x * 128;

    // cp.async indices: 2 iterations cover 128 rows x 8 quarters per tile
    const int cr = tid >> 3;             // rows 0..63 (+64 on second iter)
    const int cq = tid & 7;              // 16B quarter 0..7

    // ldmatrix per-lane address offsets
    const int lmA = lane & 15;
    const int lqA = (lane >> 4) & 1;
    uint32_t aoff[2];
#pragma unroll
    for (int fm = 0; fm < 2; fm++)
        aoff[fm] = (uint32_t)((wm * 32 + fm * 16 + lmA) * SROW + lqA * 16);
    const int bn = (lane & 7) + ((lane >> 4) << 3);
    const int bq = (lane >> 3) & 1;
    uint32_t boff[2];
#pragma unroll
    for (int fp = 0; fp < 2; fp++)
        boff[fp] = (uint32_t)((wn * 32 + fp * 16 + bn) * SROW + bq * 16);

    float acc[2][4][4];
    uint32_t crr[2][4][2];
#pragma unroll
    for (int a = 0; a < 2; a++)
#pragma unroll
        for (int b = 0; b < 4; b++) {
#pragma unroll
            for (int c = 0; c < 4; c++) acc[a][b][c] = 0.0f;
            crr[a][b][0] = 0u; crr[a][b][1] = 0u;
        }

    const int nch = K >> 6;

    auto issue = [&](int kc) {
        const uint32_t tb = sb + (uint32_t)(kc % 3) * STAGE_B;
        const int kofs = kc << 6;
#pragma unroll
        for (int j = 0; j < 2; j++) {
            const int r = cr + j * 64;
            const uint32_t so = (uint32_t)(r * SROW + cq * 16);
            const size_t goA = (size_t)(aRow0 + r) * K + kofs + cq * 8;
            const size_t goB = (size_t)(bRow0 + r) * K + kofs + cq * 8;
            cp16(tb + 0 * TILE_B + so, pAh + goA);
            if (TWOPASS) cp16(tb + 1 * TILE_B + so, pAl + goA);
            cp16(tb + 2 * TILE_B + so, pBh + goB);
        }
        CP_COMMIT();
    };

    issue(0);
    issue(1);

    for (int kc = 0; kc < nch; kc++) {
        CP_WAIT1();
        __syncthreads();
        if (kc + 2 < nch) issue(kc + 2);

        const uint32_t tb = sb + (uint32_t)(kc % 3) * STAGE_B;
#pragma unroll
        for (int h = 0; h < 4; h++) {
            const uint32_t ho = (uint32_t)(h * 32);
            uint32_t ah[2][4], al[2][4];
#pragma unroll
            for (int fm = 0; fm < 2; fm++) {
                ldsm4(ah[fm], tb + 0 * TILE_B + aoff[fm] + ho);
                if (TWOPASS) ldsm4(al[fm], tb + 1 * TILE_B + aoff[fm] + ho);
            }
            uint32_t bh[2][4];
#pragma unroll
            for (int fp = 0; fp < 2; fp++)
                ldsm4(bh[fp], tb + 2 * TILE_B + boff[fp] + ho);
#pragma unroll
            for (int fn = 0; fn < 4; fn++) {
                const uint32_t b0h = bh[fn >> 1][(fn & 1) * 2];
                const uint32_t b1h = bh[fn >> 1][(fn & 1) * 2 + 1];
#pragma unroll
                for (int fm = 0; fm < 2; fm++) {
                    mma16816(acc[fm][fn], ah[fm][0], ah[fm][1], ah[fm][2], ah[fm][3], b0h, b1h);
                    if (TWOPASS)
                        mma16816h(crr[fm][fn], al[fm][0], al[fm][1], al[fm][2], al[fm][3], b0h, b1h);
                }
            }
        }
    }

    // Epilogue: fold fp16 correction into fp32 accumulators, scale, store
    const int rowB = aRow0 + wm * 32 + g;
    const int colB = bRow0 + wn * 32 + i4 * 2;
#pragma unroll
    for (int fm = 0; fm < 2; fm++) {
#pragma unroll
        for (int fn = 0; fn < 4; fn++) {
            const int row = rowB + fm * 16;
            const int col = colB + fn * 8;
            float c0 = acc[fm][fn][0], c1 = acc[fm][fn][1];
            float c2 = acc[fm][fn][2], c3 = acc[fm][fn][3];
            if (TWOPASS) {
                float2 k0 = __half22float2(*(__half2*)&crr[fm][fn][0]);
                float2 k1 = __half22float2(*(__half2*)&crr[fm][fn][1]);
                c0 += k0.x; c1 += k0.y; c2 += k1.x; c3 += k1.y;
            }
            c0 *= alpha; c1 *= alpha; c2 *= alpha; c3 *= alpha;
            if (OUT_MODE == 0) {
                float* pc = C + z * sC;
                *(float2*)(pc + (size_t)row * N + col)       = make_float2(c0, c1);
                *(float2*)(pc + (size_t)(row + 8) * N + col) = make_float2(c2, c3);
            } else if (OUT_MODE == 1) {
                __half* ph = Ch + z * sC;
                __half* pl = Cl + z * sC;
                __half h0, h1, h2, h3, l0, l1, l2, l3;
                split2(c0, h0, l0); split2(c1, h1, l1);
                split2(c2, h2, l2); split2(c3, h3, l3);
                *(__half2*)(ph + (size_t)row * N + col)       = __halves2half2(h0, h1);
                *(__half2*)(pl + (size_t)row * N + col)       = __halves2half2(l0, l1);
                *(__half2*)(ph + (size_t)(row + 8) * N + col) = __halves2half2(h2, h3);
                *(__half2*)(pl + (size_t)(row + 8) * N + col) = __halves2half2(l2, l3);
            } else {
                __half* ph = Ch + z * sC;
                *(__half2*)(ph + (size_t)row * N + col) =
                    __halves2half2(__float2half_rn(c0), __float2half_rn(c1));
                *(__half2*)(ph + (size_t)(row + 8) * N + col) =
                    __halves2half2(__float2half_rn(c2), __float2half_rn(c3));
            }
        }
    }
}

// ---------------------------------------------------------------------------
// Transpose fp16: V[b][s][o] -> VT[b][o][s] (32x32 tiles)
// ---------------------------------------------------------------------------
__global__ __launch_bounds__(256)
void transpose_h_kernel(const __half* __restrict__ V, __half* __restrict__ T)
{
    __shared__ uint16_t t[32][34];
    const int b  = blockIdx.z;
    const int s0 = blockIdx.x << 5;
    const int o0 = blockIdx.y << 5;
    const __half* Vb = V + (size_t)b * TT * EE;
    __half* Tb = T + (size_t)b * EE * TT;
    const int tx = threadIdx.x & 31;
    const int ty = threadIdx.x >> 5;
#pragma unroll
    for (int i = 0; i < 4; i++)
        t[ty + 8 * i][tx] = __half_as_ushort(Vb[(size_t)(s0 + ty + 8 * i) * EE + o0 + tx]);
    __syncthreads();
#pragma unroll
    for (int i = 0; i < 4; i++)
        Tb[(size_t)(o0 + ty + 8 * i) * TT + s0 + tx] = __ushort_as_half(t[tx][ty + 8 * i]);
}

// ---------------------------------------------------------------------------
// Masked row softmax: S[B*T, T] fp32 -> fp16 P (hi only). mask 0 -> -inf.
// ---------------------------------------------------------------------------
__global__ __launch_bounds__(256)
void softmax_h_kernel(const float* __restrict__ S, const int* __restrict__ mask,
                      __half* __restrict__ Ph)
{
    const int row = blockIdx.x;
    const int t   = row & (TT - 1);
    const float* Srow = S + (size_t)row * TT;
    const int* mrow = mask + (size_t)t * TT;
    const int tid = threadIdx.x;

    float v[8];
    float m = -CUDART_INF_F;
#pragma unroll
    for (int i = 0; i < 8; i++) {
        int s = tid + i * 256;
        float x = (mrow[s] != 0) ? Srow[s] : -CUDART_INF_F;
        v[i] = x;
        m = fmaxf(m, x);
    }

    __shared__ float red[256];
    red[tid] = m;
    __syncthreads();
    for (int off = 128; off > 0; off >>= 1) {
        if (tid < off) red[tid] = fmaxf(red[tid], red[tid + off]);
        __syncthreads();
    }
    m = red[0];
    __syncthreads();

    float sum = 0.0f;
#pragma unroll
    for (int i = 0; i < 8; i++) {
        float e = __expf(v[i] - m);
        v[i] = e;
        sum += e;
    }
    red[tid] = sum;
    __syncthreads();
    for (int off = 128; off > 0; off >>= 1) {
        if (tid < off) red[tid] += red[tid + off];
        __syncthreads();
    }
    const float inv = 1.0f / red[0];

    __half* Phr = Ph + (size_t)row * TT;
#pragma unroll
    for (int i = 0; i < 8; i++)
        Phr[tid + i * 256] = __float2half_rn(v[i] * inv);
}

// ---------------------------------------------------------------------------
// kernel_launch
// Order: 1 split3(q,k,v)  2 convert3(W)  3 projQ  4 projK  5 projV
//        6 scores GEMM    7 transpose    8 softmax  9 PV GEMM
// ---------------------------------------------------------------------------
extern "C" void kernel_launch(void* const* d_in, const int* in_sizes, int n_in,
                              void* d_out, int out_size)
{
    const float* q    = (const float*)d_in[0];
    const float* k    = (const float*)d_in[1];
    const float* v    = (const float*)d_in[2];
    const int*   mask = (const int*)  d_in[3];
    const float* Wq   = (const float*)d_in[4];
    const float* Wk   = (const float*)d_in[5];
    const float* Wv   = (const float*)d_in[6];
    float* out = (float*)d_out;

    __half *qh, *ql, *kh, *kl, *vh, *vl;
    __half *wqh, *wkh, *wvh;
    __half *Qh, *Ql, *Kh, *Vh, *VTh, *Ph;
    float *S;
    cudaGetSymbolAddress((void**)&qh,  g_qh);  cudaGetSymbolAddress((void**)&ql,  g_ql);
    cudaGetSymbolAddress((void**)&kh,  g_kh);  cudaGetSymbolAddress((void**)&kl,  g_kl);
    cudaGetSymbolAddress((void**)&vh,  g_vh);  cudaGetSymbolAddress((void**)&vl,  g_vl);
    cudaGetSymbolAddress((void**)&wqh, g_Wqh);
    cudaGetSymbolAddress((void**)&wkh, g_Wkh);
    cudaGetSymbolAddress((void**)&wvh, g_Wvh);
    cudaGetSymbolAddress((void**)&Qh,  g_Qh);  cudaGetSymbolAddress((void**)&Ql,  g_Ql);
    cudaGetSymbolAddress((void**)&Kh,  g_Kh);
    cudaGetSymbolAddress((void**)&Vh,  g_Vh);
    cudaGetSymbolAddress((void**)&VTh, g_VTh);
    cudaGetSymbolAddress((void**)&Ph,  g_Ph);
    cudaGetSymbolAddress((void**)&S,   g_S);

    cudaFuncSetAttribute((const void*)gemm_f16pair_nt<0, 1>,
                         cudaFuncAttributeMaxDynamicSharedMemorySize, GEMM_SMEM);
    cudaFuncSetAttribute((const void*)gemm_f16pair_nt<1, 1>,
                         cudaFuncAttributeMaxDynamicSharedMemorySize, GEMM_SMEM);
    cudaFuncSetAttribute((const void*)gemm_f16pair_nt<2, 1>,
                         cudaFuncAttributeMaxDynamicSharedMemorySize, GEMM_SMEM);
    cudaFuncSetAttribute((const void*)gemm_f16pair_nt<0, 0>,
                         cudaFuncAttributeMaxDynamicSharedMemorySize, GEMM_SMEM);

    const int M = BB * TT;                   // 16384
    const size_t strQKV = (size_t)TT * EE;
    const size_t strS   = (size_t)TT * TT;
    const size_t strVT  = (size_t)EE * TT;

    // 1) Split q,k,v inputs (A-side: hi+lo)
    {
        SplitArgs a;
        a.src[0] = q;  a.src[1] = k;  a.src[2] = v;
        a.hi[0] = qh;  a.hi[1] = kh;  a.hi[2] = vh;
        a.lo[0] = ql;  a.lo[1] = kl;  a.lo[2] = vl;
        a.n = NQKV;
        dim3 gs((unsigned)(NQKV / (256 * 8)), 1, 3);
        split3_kernel<<<gs, 256>>>(a);
    }
    // 2) Convert weights (B-side: hi only)
    {
        CvtArgs a;
        a.src[0] = Wq;  a.src[1] = Wk;  a.src[2] = Wv;
        a.dst[0] = wqh; a.dst[1] = wkh; a.dst[2] = wvh;
        a.n = (size_t)EE * EE;
        dim3 gs((unsigned)((size_t)EE * EE / (256 * 8)), 1, 3);
        convert3_kernel<<<gs, 256>>>(a);
    }

    // 3-5) Projections (M=16384, N=1024, K=1024), 2-pass
    dim3 gProj(EE / 128, M / 128, 1);
    gemm_f16pair_nt<1, 1><<<gProj, 512, GEMM_SMEM>>>(qh, ql, wqh,
        nullptr, Qh, Ql, M, EE, EE, 1.0f, 0, 0, 0);
    gemm_f16pair_nt<2, 1><<<gProj, 512, GEMM_SMEM>>>(kh, kl, wkh,
        nullptr, Kh, nullptr, M, EE, EE, 1.0f, 0, 0, 0);
    gemm_f16pair_nt<2, 1><<<gProj, 512, GEMM_SMEM>>>(vh, vl, wvh,
        nullptr, Vh, nullptr, M, EE, EE, 1.0f, 0, 0, 0);

    // 6) Scores: S_b = (Q_b K_b^T) / 32   (M=N=2048, K=1024, batched), 2-pass
    dim3 gScore(TT / 128, TT / 128, BB);
    gemm_f16pair_nt<0, 1><<<gScore, 512, GEMM_SMEM>>>(Qh, Ql, Kh,
        S, nullptr, nullptr, TT, TT, EE, 1.0f / 32.0f, strQKV, strQKV, strS);

    // 7) Transpose V (fp16) -> VT
    dim3 gT(TT / 32, EE / 32, BB);
    transpose_h_kernel<<<gT, 256>>>(Vh, VTh);

    // 8) Masked softmax -> fp16 P (hi only)
    softmax_h_kernel<<<BB * TT, 256>>>(S, mask, Ph);

    // 9) Output: O_b = P_b VT_b^T  (M=2048, N=1024, K=2048, batched), 1-pass
    dim3 gOut(EE / 128, TT / 128, BB);
    gemm_f16pair_nt<0, 0><<<gOut, 512, GEMM_SMEM>>>(Ph, nullptr, VTh,
        out, nullptr, nullptr, TT, EE, TT, 1.0f, strS, strVT, strQKV);
}

// round 9
// speedup vs baseline: 2.4090x; 1.4510x over previous
#include <cuda_runtime.h>
#include <cuda_fp16.h>
#include <math_constants.h>
#include <cstdint>

// Problem constants
#define BB 8
#define TT 2048
#define EE 1024
#define NQKV ((size_t)BB * TT * EE)   // 16,777,216
#define NS   ((size_t)BB * TT * TT)   // 33,554,432

// ---------------------------------------------------------------------------
// Scratch (device globals; allocation forbidden in kernel_launch)
// ---------------------------------------------------------------------------
__device__ __half g_qh[NQKV];                   // q input fp16
__device__ __half g_kh[NQKV];                   // k input fp16
__device__ __half g_vh[NQKV];                   // v input fp16
__device__ __half g_Wqh[EE * EE];               // weights fp16
__device__ __half g_Wkh[EE * EE];
__device__ __half g_Wvh[EE * EE];
__device__ __half g_Qh[NQKV];                   // Q projected
__device__ __half g_Kh[NQKV];                   // K projected
__device__ __half g_Vh[NQKV];                   // V projected
__device__ __half g_VTh[NQKV];                  // V transposed (B in PV)
__device__ float  g_S[NS];                      // scores
__device__ __half g_Ph[NS];                     // softmax weights (A in PV)

// ---------------------------------------------------------------------------
// Helpers
// ---------------------------------------------------------------------------
__device__ __forceinline__ uint32_t smem_u32(const void* p) {
    uint32_t a;
    asm("{ .reg .u64 t; cvta.to.shared.u64 t, %1; cvt.u32.u64 %0, t; }"
        : "=r"(a) : "l"(p));
    return a;
}

__device__ __forceinline__ void cp16(uint32_t dst_smem, const void* src_gmem) {
    asm volatile("cp.async.cg.shared.global [%0], [%1], 16;"
                 :: "r"(dst_smem), "l"(__cvta_generic_to_global(src_gmem)));
}
#define CP_COMMIT() asm volatile("cp.async.commit_group;" ::: "memory")
#define CP_WAIT1()  asm volatile("cp.async.wait_group 1;"  ::: "memory")

// ldmatrix x4 (non-transposed, b16)
__device__ __forceinline__ void ldsm4(uint32_t* r, uint32_t addr) {
    asm volatile("ldmatrix.sync.aligned.m8n8.x4.shared.b16 {%0,%1,%2,%3}, [%4];"
                 : "=r"(r[0]), "=r"(r[1]), "=r"(r[2]), "=r"(r[3]) : "r"(addr));
}

// m16n8k16 fp16 -> fp32 accumulate
__device__ __forceinline__ void mma16816(float* c,
                                         uint32_t a0, uint32_t a1, uint32_t a2, uint32_t a3,
                                         uint32_t b0, uint32_t b1) {
    asm volatile(
        "mma.sync.aligned.m16n8k16.row.col.f32.f16.f16.f32 "
        "{%0,%1,%2,%3}, {%4,%5,%6,%7}, {%8,%9}, {%0,%1,%2,%3};"
        : "+f"(c[0]), "+f"(c[1]), "+f"(c[2]), "+f"(c[3])
        : "r"(a0), "r"(a1), "r"(a2), "r"(a3), "r"(b0), "r"(b1));
}

// ---------------------------------------------------------------------------
// Fused convert: fp32 -> fp16, 3 arrays per launch (z).
// ---------------------------------------------------------------------------
struct CvtArgs {
    const float* src[3];
    __half* dst[3];
    size_t n;
};

__global__ __launch_bounds__(256)
void convert3_kernel(CvtArgs a)
{
    const int z = blockIdx.z;
    const float* __restrict__ x = a.src[z];
    __half* __restrict__ d = a.dst[z];
    const size_t n = a.n;
    const size_t stride = (size_t)gridDim.x * blockDim.x * 8;

    for (size_t i = ((size_t)blockIdx.x * blockDim.x + threadIdx.x) * 8;
         i < n; i += stride) {
#pragma unroll
        for (int w = 0; w < 2; w++) {
            float4 v = *(const float4*)(x + i + w * 4);
            __half2* pd = (__half2*)(d + i + w * 4);
            pd[0] = __halves2half2(__float2half_rn(v.x), __float2half_rn(v.y));
            pd[1] = __halves2half2(__float2half_rn(v.z), __float2half_rn(v.w));
        }
    }
}

// ---------------------------------------------------------------------------
// FP16 NT GEMM on tensor cores (single pass, fp32 accumulate):
//   C[M,N] = alpha * Ah[M,K] * Bh[N,K]^T
// CTA: 128x128x64, 256 threads = 8 warps (4 x 2), warp tile 32x64.
// SMEM: 3 stages x 2 tiles (Ah, Bh), each 128 rows x 144B (128B data).
// OUT_MODE 0: fp32 C.  2: fp16 Ch.
// Requires M%128==0, N%128==0, K%64==0.
// ---------------------------------------------------------------------------
#define SROW 144
#define TILE_B (128 * SROW)            // 18432
#define STAGE_B (2 * TILE_B)           // 36864
#define GEMM_SMEM (3 * STAGE_B)        // 110592

template <int OUT_MODE>
__global__ __launch_bounds__(256, 1)
void gemm_f16_nt(const __half* __restrict__ Ah, const __half* __restrict__ Bh,
                 float* __restrict__ C, __half* __restrict__ Ch,
                 int M, int N, int K, float alpha,
                 size_t sA, size_t sB, size_t sC)
{
    extern __shared__ __align__(128) char smem[];
    const uint32_t sb = smem_u32(smem);

    const int tid  = threadIdx.x;
    const int wid  = tid >> 5;
    const int lane = tid & 31;
    const int wm   = wid >> 1;          // 0..3  (M: 4 x 32)
    const int wn   = wid & 1;           // 0..1  (N: 2 x 64)
    const int g    = lane >> 2;         // 0..7
    const int i4   = lane & 3;          // 0..3

    const size_t z = blockIdx.z;
    const __half* pAh = Ah + z * sA;
    const __half* pBh = Bh + z * sB;

    const int aRow0 = blockIdx.y * 128;
    const int bRow0 = blockIdx.x * 128;

    // cp.async indices: 4 iterations cover 128 rows x 8 quarters per tile
    const int cr = tid >> 3;             // rows 0..31 (+32j)
    const int cq = tid & 7;              // 16B quarter 0..7

    // ldmatrix per-lane address offsets
    const int lmA = lane & 15;
    const int lqA = (lane >> 4) & 1;
    uint32_t aoff[2];
#pragma unroll
    for (int fm = 0; fm < 2; fm++)
        aoff[fm] = (uint32_t)((wm * 32 + fm * 16 + lmA) * SROW + lqA * 16);
    const int bn = (lane & 7) + ((lane >> 4) << 3);
    const int bq = (lane >> 3) & 1;
    uint32_t boff[4];
#pragma unroll
    for (int fp = 0; fp < 4; fp++)
        boff[fp] = (uint32_t)((wn * 64 + fp * 16 + bn) * SROW + bq * 16);

    float acc[2][8][4];
#pragma unroll
    for (int a = 0; a < 2; a++)
#pragma unroll
        for (int b = 0; b < 8; b++)
#pragma unroll
            for (int c = 0; c < 4; c++) acc[a][b][c] = 0.0f;

    const int nch = K >> 6;

    auto issue = [&](int kc) {
        const uint32_t tb = sb + (uint32_t)(kc % 3) * STAGE_B;
        const int kofs = kc << 6;
#pragma unroll
        for (int j = 0; j < 4; j++) {
            const int r = cr + j * 32;
            const uint32_t so = (uint32_t)(r * SROW + cq * 16);
            cp16(tb + 0 * TILE_B + so, pAh + (size_t)(aRow0 + r) * K + kofs + cq * 8);
            cp16(tb + 1 * TILE_B + so, pBh + (size_t)(bRow0 + r) * K + kofs + cq * 8);
        }
        CP_COMMIT();
    };

    issue(0);
    issue(1);

    for (int kc = 0; kc < nch; kc++) {
        CP_WAIT1();
        __syncthreads();
        if (kc + 2 < nch) issue(kc + 2);

        const uint32_t tb = sb + (uint32_t)(kc % 3) * STAGE_B;
#pragma unroll
        for (int h = 0; h < 4; h++) {
            const uint32_t ho = (uint32_t)(h * 32);
            uint32_t ah[2][4];
#pragma unroll
            for (int fm = 0; fm < 2; fm++)
                ldsm4(ah[fm], tb + 0 * TILE_B + aoff[fm] + ho);
            uint32_t bh[4][4];
#pragma unroll
            for (int fp = 0; fp < 4; fp++)
                ldsm4(bh[fp], tb + 1 * TILE_B + boff[fp] + ho);
#pragma unroll
            for (int fn = 0; fn < 8; fn++) {
                const uint32_t b0 = bh[fn >> 1][(fn & 1) * 2];
                const uint32_t b1 = bh[fn >> 1][(fn & 1) * 2 + 1];
#pragma unroll
                for (int fm = 0; fm < 2; fm++)
                    mma16816(acc[fm][fn], ah[fm][0], ah[fm][1], ah[fm][2], ah[fm][3], b0, b1);
            }
        }
    }

    // Epilogue
    const int rowB = aRow0 + wm * 32 + g;
    const int colB = bRow0 + wn * 64 + i4 * 2;
#pragma unroll
    for (int fm = 0; fm < 2; fm++) {
#pragma unroll
        for (int fn = 0; fn < 8; fn++) {
            const int row = rowB + fm * 16;
            const int col = colB + fn * 8;
            const float c0 = alpha * acc[fm][fn][0];
            const float c1 = alpha * acc[fm][fn][1];
            const float c2 = alpha * acc[fm][fn][2];
            const float c3 = alpha * acc[fm][fn][3];
            if (OUT_MODE == 0) {
                float* pc = C + z * sC;
                *(float2*)(pc + (size_t)row * N + col)       = make_float2(c0, c1);
                *(float2*)(pc + (size_t)(row + 8) * N + col) = make_float2(c2, c3);
            } else {
                __half* ph = Ch + z * sC;
                *(__half2*)(ph + (size_t)row * N + col) =
                    __halves2half2(__float2half_rn(c0), __float2half_rn(c1));
                *(__half2*)(ph + (size_t)(row + 8) * N + col) =
                    __halves2half2(__float2half_rn(c2), __float2half_rn(c3));
            }
        }
    }
}

// ---------------------------------------------------------------------------
// Transpose fp16: V[b][s][o] -> VT[b][o][s] (32x32 tiles)
// ---------------------------------------------------------------------------
__global__ __launch_bounds__(256)
void transpose_h_kernel(const __half* __restrict__ V, __half* __restrict__ T)
{
    __shared__ uint16_t t[32][34];
    const int b  = blockIdx.z;
    const int s0 = blockIdx.x << 5;
    const int o0 = blockIdx.y << 5;
    const __half* Vb = V + (size_t)b * TT * EE;
    __half* Tb = T + (size_t)b * EE * TT;
    const int tx = threadIdx.x & 31;
    const int ty = threadIdx.x >> 5;
#pragma unroll
    for (int i = 0; i < 4; i++)
        t[ty + 8 * i][tx] = __half_as_ushort(Vb[(size_t)(s0 + ty + 8 * i) * EE + o0 + tx]);
    __syncthreads();
#pragma unroll
    for (int i = 0; i < 4; i++)
        Tb[(size_t)(o0 + ty + 8 * i) * TT + s0 + tx] = __ushort_as_half(t[tx][ty + 8 * i]);
}

// ---------------------------------------------------------------------------
// Masked row softmax: S[B*T, T] fp32 -> fp16 P. mask 0 -> -inf.
// ---------------------------------------------------------------------------
__global__ __launch_bounds__(256)
void softmax_h_kernel(const float* __restrict__ S, const int* __restrict__ mask,
                      __half* __restrict__ Ph)
{
    const int row = blockIdx.x;
    const int t   = row & (TT - 1);
    const float* Srow = S + (size_t)row * TT;
    const int* mrow = mask + (size_t)t * TT;
    const int tid = threadIdx.x;

    float v[8];
    float m = -CUDART_INF_F;
#pragma unroll
    for (int i = 0; i < 8; i++) {
        int s = tid + i * 256;
        float x = (mrow[s] != 0) ? Srow[s] : -CUDART_INF_F;
        v[i] = x;
        m = fmaxf(m, x);
    }

    __shared__ float red[256];
    red[tid] = m;
    __syncthreads();
    for (int off = 128; off > 0; off >>= 1) {
        if (tid < off) red[tid] = fmaxf(red[tid], red[tid + off]);
        __syncthreads();
    }
    m = red[0];
    __syncthreads();

    float sum = 0.0f;
#pragma unroll
    for (int i = 0; i < 8; i++) {
        float e = __expf(v[i] - m);
        v[i] = e;
        sum += e;
    }
    red[tid] = sum;
    __syncthreads();
    for (int off = 128; off > 0; off >>= 1) {
        if (tid < off) red[tid] += red[tid + off];
        __syncthreads();
    }
    const float inv = 1.0f / red[0];

    __half* Phr = Ph + (size_t)row * TT;
#pragma unroll
    for (int i = 0; i < 8; i++)
        Phr[tid + i * 256] = __float2half_rn(v[i] * inv);
}

// ---------------------------------------------------------------------------
// kernel_launch
// Order: 1 convert3(q,k,v)  2 convert3(W)  3 projQ  4 projK  5 projV
//        6 scores GEMM      7 transpose    8 softmax  9 PV GEMM
// ---------------------------------------------------------------------------
extern "C" void kernel_launch(void* const* d_in, const int* in_sizes, int n_in,
                              void* d_out, int out_size)
{
    const float* q    = (const float*)d_in[0];
    const float* k    = (const float*)d_in[1];
    const float* v    = (const float*)d_in[2];
    const int*   mask = (const int*)  d_in[3];
    const float* Wq   = (const float*)d_in[4];
    const float* Wk   = (const float*)d_in[5];
    const float* Wv   = (const float*)d_in[6];
    float* out = (float*)d_out;

    __half *qh, *kh, *vh, *wqh, *wkh, *wvh;
    __half *Qh, *Kh, *Vh, *VTh, *Ph;
    float *S;
    cudaGetSymbolAddress((void**)&qh,  g_qh);
    cudaGetSymbolAddress((void**)&kh,  g_kh);
    cudaGetSymbolAddress((void**)&vh,  g_vh);
    cudaGetSymbolAddress((void**)&wqh, g_Wqh);
    cudaGetSymbolAddress((void**)&wkh, g_Wkh);
    cudaGetSymbolAddress((void**)&wvh, g_Wvh);
    cudaGetSymbolAddress((void**)&Qh,  g_Qh);
    cudaGetSymbolAddress((void**)&Kh,  g_Kh);
    cudaGetSymbolAddress((void**)&Vh,  g_Vh);
    cudaGetSymbolAddress((void**)&VTh, g_VTh);
    cudaGetSymbolAddress((void**)&Ph,  g_Ph);
    cudaGetSymbolAddress((void**)&S,   g_S);

    cudaFuncSetAttribute((const void*)gemm_f16_nt<0>,
                         cudaFuncAttributeMaxDynamicSharedMemorySize, GEMM_SMEM);
    cudaFuncSetAttribute((const void*)gemm_f16_nt<2>,
                         cudaFuncAttributeMaxDynamicSharedMemorySize, GEMM_SMEM);

    const int M = BB * TT;                   // 16384
    const size_t strQKV = (size_t)TT * EE;
    const size_t strS   = (size_t)TT * TT;
    const size_t strVT  = (size_t)EE * TT;

    // 1) Convert q,k,v inputs to fp16
    {
        CvtArgs a;
        a.src[0] = q;  a.src[1] = k;  a.src[2] = v;
        a.dst[0] = qh; a.dst[1] = kh; a.dst[2] = vh;
        a.n = NQKV;
        dim3 gs((unsigned)(NQKV / (256 * 8)), 1, 3);
        convert3_kernel<<<gs, 256>>>(a);
    }
    // 2) Convert weights to fp16
    {
        CvtArgs a;
        a.src[0] = Wq;  a.src[1] = Wk;  a.src[2] = Wv;
        a.dst[0] = wqh; a.dst[1] = wkh; a.dst[2] = wvh;
        a.n = (size_t)EE * EE;
        dim3 gs((unsigned)((size_t)EE * EE / (256 * 8)), 1, 3);
        convert3_kernel<<<gs, 256>>>(a);
    }

    // 3-5) Projections (M=16384, N=1024, K=1024) -> fp16
    dim3 gProj(EE / 128, M / 128, 1);
    gemm_f16_nt<2><<<gProj, 256, GEMM_SMEM>>>(qh, wqh, nullptr, Qh,
        M, EE, EE, 1.0f, 0, 0, 0);
    gemm_f16_nt<2><<<gProj, 256, GEMM_SMEM>>>(kh, wkh, nullptr, Kh,
        M, EE, EE, 1.0f, 0, 0, 0);
    gemm_f16_nt<2><<<gProj, 256, GEMM_SMEM>>>(vh, wvh, nullptr, Vh,
        M, EE, EE, 1.0f, 0, 0, 0);

    // 6) Scores: S_b = (Q_b K_b^T) / 32   (M=N=2048, K=1024, batched) -> fp32
    dim3 gScore(TT / 128, TT / 128, BB);
    gemm_f16_nt<0><<<gScore, 256, GEMM_SMEM>>>(Qh, Kh, S, nullptr,
        TT, TT, EE, 1.0f / 32.0f, strQKV, strQKV, strS);

    // 7) Transpose V (fp16) -> VT
    dim3 gT(TT / 32, EE / 32, BB);
    transpose_h_kernel<<<gT, 256>>>(Vh, VTh);

    // 8) Masked softmax -> fp16 P
    softmax_h_kernel<<<BB * TT, 256>>>(S, mask, Ph);

    // 9) Output: O_b = P_b VT_b^T  (M=2048, N=1024, K=2048, batched) -> fp32
    dim3 gOut(EE / 128, TT / 128, BB);
    gemm_f16_nt<0><<<gOut, 256, GEMM_SMEM>>>(Ph, VTh, out, nullptr,
        TT, EE, TT, 1.0f, strS, strVT, strQKV);
}